// round 8
// baseline (speedup 1.0000x reference)
#include <cuda_runtime.h>
#include <math.h>

#define BB 4
#define SS 1024
#define TOK (BB*SS)
#define DM 1024
#define DS 128
#define NQK 4096
#define NV 4096
#define NKNOW 8192
#define NC 64
#define KC 8
#define MAXK 128
#define DHEAD 64
#define NA_QKV 512
#define NA_KNOW 1024

__device__ float g_embn[(NQK+NV+NKNOW)*DS];
__device__ float g_ceqk[NC*DS];
__device__ float g_cev[NC*DS];
__device__ float g_ceknow[NC*DS];
__device__ float g_h1[TOK*DM];
__device__ float g_hall[TOK*3*DS];
__device__ float g_tau[TOK*3];
__device__ float g_tauknow[TOK];
__device__ float g_Q[TOK*DM];
__device__ float g_K[TOK*DM];
__device__ float g_V[TOK*DM];
__device__ float g_attnpre[TOK*DM];
__device__ float g_x2[TOK*DM];
__device__ float g_h2[TOK*DM];
__device__ float g_hknow[TOK*DS];
__device__ int   g_idsQ[TOK*NA_QKV];
__device__ int   g_idsK[TOK*NA_QKV];
__device__ int   g_idsV[TOK*NA_QKV];
__device__ int   g_idsKn[TOK*NA_KNOW];
__device__ float g_valsQ[TOK*NA_QKV];
__device__ float g_valsK[TOK*NA_QKV];
__device__ float g_valsV[TOK*NA_QKV];
__device__ float g_valsKn[TOK*NA_KNOW];
__device__ int   g_cntQ[TOK];
__device__ int   g_cntK[TOK];
__device__ int   g_cntV[TOK];
__device__ int   g_cntKn[TOK];
__device__ float g_cfreq[4*NC];
__device__ float g_nfreqQ[NQK];
__device__ float g_nfreqK[NQK];
__device__ float g_nfreqV[NV];
__device__ float g_nfreqKn[NKNOW];
__device__ int   g_ccount[4*NC];
__device__ int   g_clist[4*NC*TOK];
__device__ int   g_top8[4*TOK*KC];
__device__ float g_seg[(size_t)TOK*NA_KNOW];

__device__ __forceinline__ float warp_sum(float v){
#pragma unroll
  for (int o=16;o;o>>=1) v += __shfl_xor_sync(0xffffffffu, v, o);
  return v;
}
__device__ __forceinline__ float warp_max(float v){
#pragma unroll
  for (int o=16;o;o>>=1) v = fmaxf(v, __shfl_xor_sync(0xffffffffu, v, o));
  return v;
}
__device__ __forceinline__ float block_sum(float v, float* s){
  v = warp_sum(v);
  int w = threadIdx.x>>5, l = threadIdx.x&31;
  if (l==0) s[w]=v;
  __syncthreads();
  if (w==0){ float r=(l<8)?s[l]:0.f; r=warp_sum(r); if(l==0) s[0]=r; }
  __syncthreads();
  float r=s[0]; __syncthreads(); return r;
}
__device__ __forceinline__ float block_max(float v, float* s){
  v = warp_max(v);
  int w = threadIdx.x>>5, l = threadIdx.x&31;
  if (l==0) s[w]=v;
  __syncthreads();
  if (w==0){ float r=(l<8)?s[l]:-3.4e38f; r=warp_max(r); if(l==0) s[0]=r; }
  __syncthreads();
  float r=s[0]; __syncthreads(); return r;
}

__global__ __launch_bounds__(256) void dawn_ln(const float* __restrict__ x,
                                               const float* __restrict__ sc,
                                               const float* __restrict__ bi,
                                               float* __restrict__ out, int dozero){
  int t = blockIdx.x, tid = threadIdx.x;
  if (dozero){
    int f = t*256 + tid;
    if (f < 256) g_cfreq[f]=0.f;
    else if (f < 4352) g_nfreqQ[f-256]=0.f;
    else if (f < 8448) g_nfreqK[f-4352]=0.f;
    else if (f < 12544) g_nfreqV[f-8448]=0.f;
    else if (f < 20736) g_nfreqKn[f-12544]=0.f;
    else if (f < 20992) g_ccount[f-20736]=0;
  }
  __shared__ float sred[32];
  float4 xv = ((const float4*)(x + (size_t)t*DM))[tid];
  float mean = block_sum(xv.x+xv.y+xv.z+xv.w, sred) * (1.f/DM);
  float dx=xv.x-mean, dy=xv.y-mean, dz=xv.z-mean, dw=xv.w-mean;
  float var = block_sum(dx*dx+dy*dy+dz*dz+dw*dw, sred) * (1.f/DM);
  float inv = rsqrtf(var + 1e-6f);
  float4 s4 = ((const float4*)sc)[tid];
  float4 b4 = ((const float4*)bi)[tid];
  float4 o; o.x=dx*inv*s4.x+b4.x; o.y=dy*inv*s4.y+b4.y;
  o.z=dz*inv*s4.z+b4.z; o.w=dw*inv*s4.w+b4.w;
  ((float4*)(out + (size_t)t*DM))[tid] = o;
}

__global__ __launch_bounds__(256) void dawn_normall(const float* __restrict__ emb,
                                                    const float* __restrict__ c0,
                                                    const float* __restrict__ c1,
                                                    const float* __restrict__ c2){
  int row = blockIdx.x*8 + (threadIdx.x>>5);
  int lane = threadIdx.x & 31;
  const float* src; float* dst;
  if (row < NQK+NV+NKNOW){ src = emb + (size_t)row*DS; dst = g_embn + (size_t)row*DS; }
  else {
    int r = row - (NQK+NV+NKNOW);
    if (r < NC){ src = c0 + r*DS; dst = g_ceqk + r*DS; }
    else if (r < 2*NC){ src = c1 + (r-NC)*DS; dst = g_cev + (r-NC)*DS; }
    else if (r < 3*NC){ src = c2 + (r-2*NC)*DS; dst = g_ceknow + (r-2*NC)*DS; }
    else return;
  }
  float4 v = ((const float4*)src)[lane];
  float s = warp_sum(v.x*v.x+v.y*v.y+v.z*v.z+v.w*v.w);
  float inv = 1.f/(sqrtf(s)+1e-8f);
  float4 o; o.x=v.x*inv; o.y=v.y*inv; o.z=v.z*inv; o.w=v.w*inv;
  ((float4*)dst)[lane] = o;
}

// 128x128 tile, 8x8 micro (split rows/cols +64), K step 8
template<bool BIAS, bool RES>
__global__ __launch_bounds__(256) void dawn_sgemm(const float* __restrict__ A,
                                                  const float* __restrict__ B,
                                                  const float* __restrict__ bias,
                                                  const float* __restrict__ R,
                                                  float* __restrict__ C,
                                                  int M, int N, int K){
  __shared__ __align__(16) float As[8][132];
  __shared__ __align__(16) float Bs[8][132];
  int mb = blockIdx.y*128, nb = blockIdx.x*128;
  int tid = threadIdx.x;
  int tm = (tid>>4)<<2, tn = (tid&15)<<2;
  float acc[8][8];
#pragma unroll
  for (int i=0;i<8;i++)
#pragma unroll
    for (int j=0;j<8;j++) acc[i][j]=0.f;
  int ar = tid>>1, ak = (tid&1)<<2;
  int bk = tid>>5, bn = (tid&31)<<2;
  const float* Aptr = A + (size_t)(mb+ar)*K + ak;
  const float* Bptr = B + (size_t)bk*N + nb + bn;
  for (int k0=0;k0<K;k0+=8){
    float4 a = *(const float4*)(Aptr + k0);
    As[ak+0][ar]=a.x; As[ak+1][ar]=a.y; As[ak+2][ar]=a.z; As[ak+3][ar]=a.w;
    *(float4*)(&Bs[bk][bn]) = *(const float4*)(Bptr + (size_t)k0*N);
    __syncthreads();
#pragma unroll
    for (int k=0;k<8;k++){
      float4 a0 = *(const float4*)(&As[k][tm]);
      float4 a1 = *(const float4*)(&As[k][tm+64]);
      float4 b0 = *(const float4*)(&Bs[k][tn]);
      float4 b1 = *(const float4*)(&Bs[k][tn+64]);
      float ra[8] = {a0.x,a0.y,a0.z,a0.w,a1.x,a1.y,a1.z,a1.w};
      float rb[8] = {b0.x,b0.y,b0.z,b0.w,b1.x,b1.y,b1.z,b1.w};
#pragma unroll
      for (int i=0;i<8;i++)
#pragma unroll
        for (int j=0;j<8;j++) acc[i][j] += ra[i]*rb[j];
    }
    __syncthreads();
  }
#pragma unroll
  for (int i=0;i<8;i++){
    int row = mb + ((i<4)? (tm+i) : (tm+64+i-4));
#pragma unroll
    for (int jh=0;jh<2;jh++){
      int col = nb + tn + jh*64;
      size_t off = (size_t)row*N + col;
      float4 v;
      v.x=acc[i][jh*4+0]; v.y=acc[i][jh*4+1]; v.z=acc[i][jh*4+2]; v.w=acc[i][jh*4+3];
      if (BIAS){
        const float4 b4 = *(const float4*)(bias + col);
        v.x+=b4.x; v.y+=b4.y; v.z+=b4.z; v.w+=b4.w;
      }
      if (RES){
        const float4 r4 = *(const float4*)(R + off);
        v.x+=r4.x; v.y+=r4.y; v.z+=r4.z; v.w+=r4.w;
      }
      *(float4*)(C + off) = v;
    }
  }
}

__global__ __launch_bounds__(256) void dawn_tau(const float* __restrict__ h,
                                                const float* __restrict__ W,
                                                const float* __restrict__ bias,
                                                float* __restrict__ out, int ncols){
  int t = blockIdx.x, tid = threadIdx.x;
  float p[3] = {0.f,0.f,0.f};
  const float* row = h + (size_t)t*DM;
  for (int d=tid; d<DM; d+=256){
    float xv = row[d];
    for (int j=0;j<ncols;j++) p[j] += xv * W[d*ncols+j];
  }
  __shared__ float sred[24];
  int w = tid>>5, l = tid&31;
  for (int j=0;j<ncols;j++){
    float s = warp_sum(p[j]);
    if (l==0) sred[w*3+j]=s;
  }
  __syncthreads();
  if (tid < ncols){
    float s=0.f;
    for (int ww=0;ww<8;ww++) s += sred[ww*3+tid];
    out[(size_t)t*ncols+tid] = s + bias[tid];
  }
}

__global__ __launch_bounds__(256) void dawn_gateA(
    const float* __restrict__ hsrc, int hstride, int hoff,
    const float* __restrict__ ce, float* __restrict__ cfreq,
    int* __restrict__ top8, int* __restrict__ ccount, int* __restrict__ clist){
  const int t = blockIdx.x, tid = threadIdx.x;
  const int warp = tid>>5, lane = tid&31;
  __shared__ __align__(16) float sh[DS];
  __shared__ float sc[NC];
  __shared__ int stop8[KC];
  if (tid < DS) sh[tid] = hsrc[(size_t)t*hstride + hoff + tid];
  __syncthreads();
  for (int c = warp*8; c < warp*8+8; ++c){
    const float* cr = ce + c*DS;
    float p = sh[lane]*cr[lane] + sh[lane+32]*cr[lane+32]
            + sh[lane+64]*cr[lane+64] + sh[lane+96]*cr[lane+96];
    p = warp_sum(p);
    if (lane==0) sc[c]=p;
  }
  __syncthreads();
  if (warp==0){
    float v0=sc[lane], v1=sc[lane+32];
    float m = warp_max(fmaxf(v0,v1));
    float e0=expf(v0-m), e1=expf(v1-m);
    float inv = 1.f/warp_sum(e0+e1);
    atomicAdd(&cfreq[lane],    e0*inv);
    atomicAdd(&cfreq[lane+32], e1*inv);
    float a0=v0, a1=v1;
    for (int it=0; it<KC; ++it){
      float mv; int mi;
      if (a0>=a1){ mv=a0; mi=lane; } else { mv=a1; mi=lane+32; }
#pragma unroll
      for (int o=16;o;o>>=1){
        float ov = __shfl_xor_sync(0xffffffffu, mv, o);
        int   oi = __shfl_xor_sync(0xffffffffu, mi, o);
        if (ov>mv || (ov==mv && oi<mi)){ mv=ov; mi=oi; }
      }
      if (lane==0) stop8[it]=mi;
      mi = __shfl_sync(0xffffffffu, mi, 0);
      if (mi==lane) a0=-3.4e38f;
      else if (mi==lane+32) a1=-3.4e38f;
    }
  }
  __syncthreads();
  if (tid < KC){
    int c = stop8[tid];
    top8[t*KC + tid] = c;
    int pos = atomicAdd(&ccount[c], 1);
    clist[c*TOK + pos] = t | (tid<<16);
  }
}

template<int CS>
__global__ __launch_bounds__(256) void dawn_gateB(
    const float* __restrict__ hsrc, int hstride, int hoff,
    const float* __restrict__ tausrc, int taustride, int tauoff,
    const float* __restrict__ emb,
    const int* __restrict__ clist, const int* __restrict__ ccount,
    float* __restrict__ seg){
  const int NA = CS*KC;
  int c = blockIdx.y, chunk = blockIdx.x, ntile = blockIdx.z;
  int count = ccount[c];
  int t0 = chunk*64;
  if (t0 >= count) return;
  int nTok = count - t0; if (nTok > 64) nTok = 64;
  extern __shared__ __align__(16) float smem[];
  float* hT = smem;
  float* eT = smem + 128*68;
  __shared__ int toks[64]; __shared__ int slots[64]; __shared__ float taus[64];
  int tid = threadIdx.x;
  if (tid < 64){
    if (tid < nTok){
      int e = clist[c*TOK + t0 + tid];
      int t = e & 0xFFFF;
      toks[tid] = t; slots[tid] = e >> 16;
      taus[tid] = tausrc[(size_t)t*taustride + tauoff];
    } else toks[tid] = 0x7FFFFFFF;
  }
  __syncthreads();
  for (int i = tid; i < 64*128; i += 256){
    int tt = i >> 7, k = i & 127;
    float v = 0.f;
    if (tt < nTok) v = hsrc[(size_t)toks[tt]*hstride + hoff + k];
    hT[k*68 + tt] = v;
  }
  const float* ebase = emb + ((size_t)c*CS + ntile*64)*DS;
  for (int i = tid; i < 64*128; i += 256){
    int n = i >> 7, k = i & 127;
    eT[k*68 + n] = ebase[(size_t)n*DS + k];
  }
  __syncthreads();
  int tt0 = (tid>>4)<<2, tn0 = (tid&15)<<2;
  float acc[4][4];
#pragma unroll
  for (int a=0;a<4;a++)
#pragma unroll
    for (int b=0;b<4;b++) acc[a][b]=0.f;
#pragma unroll 4
  for (int k=0;k<128;k++){
    float4 hv = *(const float4*)(hT + k*68 + tt0);
    float4 ev = *(const float4*)(eT + k*68 + tn0);
    acc[0][0]+=hv.x*ev.x; acc[0][1]+=hv.x*ev.y; acc[0][2]+=hv.x*ev.z; acc[0][3]+=hv.x*ev.w;
    acc[1][0]+=hv.y*ev.x; acc[1][1]+=hv.y*ev.y; acc[1][2]+=hv.y*ev.z; acc[1][3]+=hv.y*ev.w;
    acc[2][0]+=hv.z*ev.x; acc[2][1]+=hv.z*ev.y; acc[2][2]+=hv.z*ev.z; acc[2][3]+=hv.z*ev.w;
    acc[3][0]+=hv.w*ev.x; acc[3][1]+=hv.w*ev.y; acc[3][2]+=hv.w*ev.z; acc[3][3]+=hv.w*ev.w;
  }
#pragma unroll
  for (int a=0;a<4;a++){
    int j = tt0 + a;
    if (j >= nTok) break;
    float tau = taus[j];
    size_t base = (size_t)toks[j]*NA + (size_t)slots[j]*CS + ntile*64 + tn0;
#pragma unroll
    for (int b=0;b<4;b++){
      float raw = acc[a][b] - tau;
      float e;
      if (raw > 0.f)        e = expf(raw) - 1.0f;
      else if (raw < -5.f)  e = 0.f;
      else {
        float gate = 1e-8f*expf(raw);
        e = expf(gate) - 1.0f;
      }
      seg[base + b] = e;
    }
  }
}

template<int CS>
__global__ __launch_bounds__(256) void dawn_gateC(
    const float* __restrict__ seg_g, const int* __restrict__ top8,
    int* __restrict__ ids, float* __restrict__ vals, int* __restrict__ cnt,
    float* __restrict__ nfreq){
  const int NA = CS*KC;
  const int t = blockIdx.x, tid = threadIdx.x;
  const int warp = tid>>5, lane = tid&31;
  __shared__ float seg[CS*KC];
  __shared__ int stop8[KC];
  __shared__ float sred[32];
  __shared__ int hist[256];
  __shared__ int sfx[257];
  __shared__ int wtot[8];
  __shared__ unsigned s_prefix;
  __shared__ int s_remaining;
  __shared__ int scnt;
  if (tid < KC) stop8[tid] = top8[t*KC + tid];
  if (tid == 0){ scnt=0; s_prefix=0u; s_remaining=MAXK; }
  for (int i=tid;i<NA;i+=256) seg[i] = seg_g[(size_t)t*NA + i];
  __syncthreads();
  for (int pass=3; pass>=0; --pass){
    hist[tid]=0;
    __syncthreads();
    unsigned maskKnown = (pass==3)?0u:(0xFFFFFFFFu << ((pass+1)*8));
    unsigned pfx = s_prefix;
    for (int i=tid;i<NA;i+=256){
      unsigned key = __float_as_uint(seg[i]);
      if ((key & maskKnown) == pfx)
        atomicAdd(&hist[(key >> (pass*8)) & 255], 1);
    }
    __syncthreads();
    int v = hist[255 - tid];
    int sc2 = v;
#pragma unroll
    for (int o=1;o<32;o<<=1){ int t2=__shfl_up_sync(0xffffffffu, sc2, o); if (lane>=o) sc2+=t2; }
    if (lane==31) wtot[warp]=sc2;
    __syncthreads();
    int off=0;
    for (int j=0;j<warp;j++) off+=wtot[j];
    sfx[255 - tid] = sc2 + off;
    if (tid==0) sfx[256]=0;
    __syncthreads();
    int rem = s_remaining;
    if (sfx[tid] >= rem && sfx[tid+1] < rem){
      s_prefix = pfx | ((unsigned)tid << (pass*8));
      s_remaining = rem - sfx[tid+1];
    }
    __syncthreads();
  }
  float thr = __uint_as_float(s_prefix);
  float ps=0.f, pm=0.f;
  for (int i=tid;i<NA;i+=256){
    float e = seg[i];
    if (e >= thr) ps += e;
    pm = fmaxf(pm, e);
  }
  float tot = block_sum(ps, sred);
  float mx  = block_max(pm, sred);
  float scale = tanhf(mx) / (tot + 1e-8f);
  for (int i=tid;i<NA;i+=256){
    float e = seg[i];
    if (e >= thr && e > 0.f){
      int pos = atomicAdd(&scnt, 1);
      int nid = stop8[i/CS]*CS + (i%CS);
      float v = e*scale;
      ids[(size_t)t*NA+pos]  = nid;
      vals[(size_t)t*NA+pos] = v;
      atomicAdd(&nfreq[nid], v);
    }
  }
  __syncthreads();
  if (tid==0) cnt[t]=scnt;
}

// warp-per-2-neurons emit, fp32, split-partial dots for ILP
__global__ __launch_bounds__(256) void dawn_emit(const float* __restrict__ h,
                                                 const float* __restrict__ W,
                                                 const int* __restrict__ idsA,
                                                 const float* __restrict__ valsA,
                                                 const int* __restrict__ cntA,
                                                 int cap,
                                                 float* __restrict__ out,
                                                 const float* __restrict__ resid){
  int t = blockIdx.x, tid = threadIdx.x;
  int w = tid>>5, lane = tid&31;
  __shared__ __align__(16) float sacc[8*DM];
  const int* ids = idsA + (size_t)t*cap;
  const float* vals = valsA + (size_t)t*cap;
  int n = cntA[t];
  float4 h4[8];
  const float4* hrow = (const float4*)(h + (size_t)t*DM);
#pragma unroll
  for (int j=0;j<8;j++) h4[j] = hrow[lane + 32*j];
  float4 acc[8];
#pragma unroll
  for (int j=0;j<8;j++) acc[j] = make_float4(0.f,0.f,0.f,0.f);
  for (int i=w*2; i<n; i+=16){
    int nid0 = ids[i];
    float v0 = vals[i];
    bool has1 = (i+1 < n);
    int nid1 = has1 ? ids[i+1] : nid0;
    float v1 = has1 ? vals[i+1] : 0.f;
    const float4* W0 = (const float4*)(W + (size_t)nid0*DM);
    const float4* W1 = (const float4*)(W + (size_t)nid1*DM);
    float4 r0[8], r1[8];
#pragma unroll
    for (int j=0;j<8;j++){ r0[j] = W0[lane + 32*j]; r1[j] = W1[lane + 32*j]; }
    float p0a=0.f, p0b=0.f, p1a=0.f, p1b=0.f;
#pragma unroll
    for (int j=0;j<8;j+=2){
      p0a += r0[j].x*h4[j].x + r0[j].y*h4[j].y + r0[j].z*h4[j].z + r0[j].w*h4[j].w;
      p1a += r1[j].x*h4[j].x + r1[j].y*h4[j].y + r1[j].z*h4[j].z + r1[j].w*h4[j].w;
      p0b += r0[j+1].x*h4[j+1].x + r0[j+1].y*h4[j+1].y + r0[j+1].z*h4[j+1].z + r0[j+1].w*h4[j+1].w;
      p1b += r1[j+1].x*h4[j+1].x + r1[j+1].y*h4[j+1].y + r1[j+1].z*h4[j+1].z + r1[j+1].w*h4[j+1].w;
    }
    float p0 = warp_sum(p0a+p0b);
    float p1 = warp_sum(p1a+p1b);
    float a0 = p0*v0, a1 = p1*v1;
#pragma unroll
    for (int j=0;j<8;j++){
      acc[j].x += a0*r0[j].x + a1*r1[j].x;
      acc[j].y += a0*r0[j].y + a1*r1[j].y;
      acc[j].z += a0*r0[j].z + a1*r1[j].z;
      acc[j].w += a0*r0[j].w + a1*r1[j].w;
    }
  }
  float4* s4 = (float4*)sacc;
#pragma unroll
  for (int j=0;j<8;j++) s4[w*256 + lane + 32*j] = acc[j];
  __syncthreads();
  float4 o = s4[tid];
#pragma unroll
  for (int ww=1; ww<8; ww++){
    float4 v = s4[ww*256 + tid];
    o.x+=v.x; o.y+=v.y; o.z+=v.z; o.w+=v.w;
  }
  if (resid){
    float4 r = ((const float4*)(resid + (size_t)t*DM))[tid];
    o.x+=r.x; o.y+=r.y; o.z+=r.z; o.w+=r.w;
  }
  ((float4*)(out + (size_t)t*DM))[tid] = o;
}

#define ATTN_SMEM (4*64*68*4)
__global__ __launch_bounds__(256) void dawn_attn(const float* __restrict__ Q,
                                                 const float* __restrict__ K,
                                                 const float* __restrict__ V,
                                                 float* __restrict__ O){
  extern __shared__ __align__(16) float smem[];
  float* Qs = smem;
  float* Ks = Qs + 64*68;
  float* Vs = Ks + 64*68;
  float* Ps = Vs + 64*68;
  int qt = blockIdx.x, bh = blockIdx.y;
  int b = bh>>4, h = bh&15;
  int tid = threadIdx.x, warp = tid>>5, lane = tid&31;
  size_t tok0 = (size_t)b*SS;
  int qbase = qt*64;
  for (int e=tid; e<64*64; e+=256){
    int r=e>>6, d=e&63;
    Qs[r*68+d] = Q[(tok0 + qbase + r)*DM + h*DHEAD + d] * 0.125f;
  }
  float Oa[8][2], m[8], l[8];
#pragma unroll
  for (int i=0;i<8;i++){ Oa[i][0]=0.f; Oa[i][1]=0.f; m[i]=-3.4e38f; l[i]=0.f; }
  int c0 = lane, c1 = lane+32;
  for (int kt=0; kt<=qt; ++kt){
    __syncthreads();
    for (int e=tid; e<64*64; e+=256){
      int r=e>>6, d=e&63;
      Ks[r*68+d] = K[(tok0 + kt*64 + r)*DM + h*DHEAD + d];
      Vs[r*68+d] = V[(tok0 + kt*64 + r)*DM + h*DHEAD + d];
    }
    __syncthreads();
#pragma unroll
    for (int qr=0;qr<8;qr++){
      int row = warp*8+qr;
      float s0=0.f, s1=0.f;
#pragma unroll
      for (int d4=0; d4<16; d4++){
        float4 qv = *(const float4*)(Qs + row*68 + d4*4);
        float4 k0 = *(const float4*)(Ks + c0*68 + d4*4);
        float4 k1 = *(const float4*)(Ks + c1*68 + d4*4);
        s0 += qv.x*k0.x + qv.y*k0.y + qv.z*k0.z + qv.w*k0.w;
        s1 += qv.x*k1.x + qv.y*k1.y + qv.z*k1.z + qv.w*k1.w;
      }
      int qg = qbase + row;
      if (kt*64 + c0 > qg) s0 = -3.4e38f;
      if (kt*64 + c1 > qg) s1 = -3.4e38f;
      float tm = warp_max(fmaxf(s0,s1));
      float mn = fmaxf(m[qr], tm);
      float corr = __expf(m[qr]-mn);
      float p0 = __expf(s0-mn), p1 = __expf(s1-mn);
      float rs = warp_sum(p0+p1);
      l[qr] = l[qr]*corr + rs;
      m[qr] = mn;
      Oa[qr][0]*=corr; Oa[qr][1]*=corr;
      Ps[row*68+c0]=p0; Ps[row*68+c1]=p1;
    }
    __syncwarp();
#pragma unroll
    for (int k4=0;k4<16;k4++){
      float vv0[4], vv1[4];
#pragma unroll
      for (int kk=0;kk<4;kk++){
        vv0[kk]=Vs[(k4*4+kk)*68+c0];
        vv1[kk]=Vs[(k4*4+kk)*68+c1];
      }
#pragma unroll
      for (int qr=0;qr<8;qr++){
        float4 pv = *(const float4*)(Ps + (warp*8+qr)*68 + k4*4);
        Oa[qr][0] += pv.x*vv0[0] + pv.y*vv0[1] + pv.z*vv0[2] + pv.w*vv0[3];
        Oa[qr][1] += pv.x*vv1[0] + pv.y*vv1[1] + pv.z*vv1[2] + pv.w*vv1[3];
      }
    }
  }
  __syncthreads();
#pragma unroll
  for (int qr=0;qr<8;qr++){
    int row = warp*8+qr;
    float invl = 1.f/l[qr];
    Ps[row*68+c0]=Oa[qr][0]*invl;
    Ps[row*68+c1]=Oa[qr][1]*invl;
  }
  __syncthreads();
  for (int e=tid;e<64*64;e+=256){
    int r=e>>6, d=e&63;
    O[(tok0 + qbase + r)*DM + h*DHEAD + d] = Ps[r*68+d];
  }
}

__global__ __launch_bounds__(256) void dawn_aux(float* __restrict__ out, int out_size){
  if (out_size <= TOK*DM) return;
  int tid = threadIdx.x;
  __shared__ float sred[32];
  float a = 0.f;
  const float invT = 1.f/(float)TOK;
  for (int i=tid;i<4*NC;i+=256){
    float d = g_cfreq[i]*invT - 1.f/(float)NC;
    a += d*d*(float)NC;
  }
  for (int i=tid;i<NQK;i+=256){
    float d;
    d = g_nfreqQ[i]*invT - 1.f/(float)NQK; a += d*d*(float)NQK;
    d = g_nfreqK[i]*invT - 1.f/(float)NQK; a += d*d*(float)NQK;
    d = g_nfreqV[i]*invT - 1.f/(float)NV;  a += d*d*(float)NV;
  }
  for (int i=tid;i<NKNOW;i+=256){
    float d = g_nfreqKn[i]*invT - 1.f/(float)NKNOW;
    a += d*d*(float)NKNOW;
  }
  float tot = block_sum(a, sred);
  if (tid==0) out[TOK*DM] = tot;
}

#define GATEB_SMEM (2*128*68*4)

extern "C" void kernel_launch(void* const* d_in, const int* in_sizes, int n_in,
                              void* d_out, int out_size){
  const float* x           = (const float*)d_in[0];
  const float* neuron_emb  = (const float*)d_in[1];
  const float* proj_attn_k = (const float*)d_in[2];
  const float* proj_attn_b = (const float*)d_in[3];
  const float* tau_attn_k  = (const float*)d_in[4];
  const float* tau_attn_b  = (const float*)d_in[5];
  const float* proj_know_k = (const float*)d_in[6];
  const float* proj_know_b = (const float*)d_in[7];
  const float* tau_know_k  = (const float*)d_in[8];
  const float* tau_know_b  = (const float*)d_in[9];
  const float* ce_qk       = (const float*)d_in[10];
  const float* ce_v        = (const float*)d_in[11];
  const float* ce_know     = (const float*)d_in[12];
  const float* qk_neurons  = (const float*)d_in[13];
  const float* v_neurons   = (const float*)d_in[14];
  const float* know_neurons= (const float*)d_in[15];
  const float* expand_O    = (const float*)d_in[16];
  const float* ln1s = (const float*)d_in[17];
  const float* ln1b = (const float*)d_in[18];
  const float* ln2s = (const float*)d_in[19];
  const float* ln2b = (const float*)d_in[20];
  float* out = (float*)d_out;

  static bool attr_done = false;
  if (!attr_done){
    cudaFuncSetAttribute(dawn_attn, cudaFuncAttributeMaxDynamicSharedMemorySize, ATTN_SMEM);
    cudaFuncSetAttribute(dawn_gateB<64>,  cudaFuncAttributeMaxDynamicSharedMemorySize, GATEB_SMEM);
    cudaFuncSetAttribute(dawn_gateB<128>, cudaFuncAttributeMaxDynamicSharedMemorySize, GATEB_SMEM);
    attr_done = true;
  }

  float *p_embn,*p_ceqk,*p_cev,*p_ceknow,*p_h1,*p_hall,*p_tau,*p_tauknow;
  float *p_Q,*p_K,*p_V,*p_attnpre,*p_x2,*p_h2,*p_hknow,*p_seg;
  int *p_idsQ,*p_idsK,*p_idsV,*p_idsKn,*p_cntQ,*p_cntK,*p_cntV,*p_cntKn;
  int *p_ccount,*p_clist,*p_top8;
  float *p_valsQ,*p_valsK,*p_valsV,*p_valsKn,*p_cfreq,*p_nfreqQ,*p_nfreqK,*p_nfreqV,*p_nfreqKn;
  cudaGetSymbolAddress((void**)&p_embn, g_embn);
  cudaGetSymbolAddress((void**)&p_ceqk, g_ceqk);
  cudaGetSymbolAddress((void**)&p_cev, g_cev);
  cudaGetSymbolAddress((void**)&p_ceknow, g_ceknow);
  cudaGetSymbolAddress((void**)&p_h1, g_h1);
  cudaGetSymbolAddress((void**)&p_hall, g_hall);
  cudaGetSymbolAddress((void**)&p_tau, g_tau);
  cudaGetSymbolAddress((void**)&p_tauknow, g_tauknow);
  cudaGetSymbolAddress((void**)&p_Q, g_Q);
  cudaGetSymbolAddress((void**)&p_K, g_K);
  cudaGetSymbolAddress((void**)&p_V, g_V);
  cudaGetSymbolAddress((void**)&p_attnpre, g_attnpre);
  cudaGetSymbolAddress((void**)&p_x2, g_x2);
  cudaGetSymbolAddress((void**)&p_h2, g_h2);
  cudaGetSymbolAddress((void**)&p_hknow, g_hknow);
  cudaGetSymbolAddress((void**)&p_seg, g_seg);
  cudaGetSymbolAddress((void**)&p_idsQ, g_idsQ);
  cudaGetSymbolAddress((void**)&p_idsK, g_idsK);
  cudaGetSymbolAddress((void**)&p_idsV, g_idsV);
  cudaGetSymbolAddress((void**)&p_idsKn, g_idsKn);
  cudaGetSymbolAddress((void**)&p_valsQ, g_valsQ);
  cudaGetSymbolAddress((void**)&p_valsK, g_valsK);
  cudaGetSymbolAddress((void**)&p_valsV, g_valsV);
  cudaGetSymbolAddress((void**)&p_valsKn, g_valsKn);
  cudaGetSymbolAddress((void**)&p_cntQ, g_cntQ);
  cudaGetSymbolAddress((void**)&p_cntK, g_cntK);
  cudaGetSymbolAddress((void**)&p_cntV, g_cntV);
  cudaGetSymbolAddress((void**)&p_cntKn, g_cntKn);
  cudaGetSymbolAddress((void**)&p_cfreq, g_cfreq);
  cudaGetSymbolAddress((void**)&p_nfreqQ, g_nfreqQ);
  cudaGetSymbolAddress((void**)&p_nfreqK, g_nfreqK);
  cudaGetSymbolAddress((void**)&p_nfreqV, g_nfreqV);
  cudaGetSymbolAddress((void**)&p_nfreqKn, g_nfreqKn);
  cudaGetSymbolAddress((void**)&p_ccount, g_ccount);
  cudaGetSymbolAddress((void**)&p_clist, g_clist);
  cudaGetSymbolAddress((void**)&p_top8, g_top8);

  // 1: LN1 (+ zero scratch)   2: tau   3: row-normalize   4: proj GEMM (profiled)
  dawn_ln<<<TOK,256>>>(x, ln1s, ln1b, p_h1, 1);
  dawn_tau<<<TOK,256>>>(p_h1, tau_attn_k, tau_attn_b, p_tau, 3);
  dawn_normall<<<(NQK+NV+NKNOW+3*NC)/8,256>>>(neuron_emb, ce_qk, ce_v, ce_know);
  dawn_sgemm<true,false><<<dim3(3,32),256>>>(p_h1, proj_attn_k, proj_attn_b, nullptr, p_hall, TOK, 3*DS, DM);

  // Q gate
  dawn_gateA<<<TOK,256>>>(p_hall, 3*DS, 0, p_ceqk, p_cfreq+0, p_top8+0*TOK*KC, p_ccount+0*NC, p_clist+0*NC*TOK);
  dawn_gateB<64><<<dim3(64,NC,1),256,GATEB_SMEM>>>(p_hall, 3*DS, 0, p_tau, 3, 0, p_embn, p_clist+0*NC*TOK, p_ccount+0*NC, p_seg);
  dawn_gateC<64><<<TOK,256>>>(p_seg, p_top8+0*TOK*KC, p_idsQ, p_valsQ, p_cntQ, p_nfreqQ);
  dawn_emit<<<TOK,256>>>(p_h1, qk_neurons, p_idsQ, p_valsQ, p_cntQ, NA_QKV, p_Q, nullptr);

  // K gate
  dawn_gateA<<<TOK,256>>>(p_hall, 3*DS, 128, p_ceqk, p_cfreq+64, p_top8+1*TOK*KC, p_ccount+1*NC, p_clist+1*NC*TOK);
  dawn_gateB<64><<<dim3(64,NC,1),256,GATEB_SMEM>>>(p_hall, 3*DS, 128, p_tau, 3, 1, p_embn, p_clist+1*NC*TOK, p_ccount+1*NC, p_seg);
  dawn_gateC<64><<<TOK,256>>>(p_seg, p_top8+1*TOK*KC, p_idsK, p_valsK, p_cntK, p_nfreqK);
  dawn_emit<<<TOK,256>>>(p_h1, qk_neurons, p_idsK, p_valsK, p_cntK, NA_QKV, p_K, nullptr);

  // V gate
  dawn_gateA<<<TOK,256>>>(p_hall, 3*DS, 256, p_cev, p_cfreq+128, p_top8+2*TOK*KC, p_ccount+2*NC, p_clist+2*NC*TOK);
  dawn_gateB<64><<<dim3(64,NC,1),256,GATEB_SMEM>>>(p_hall, 3*DS, 256, p_tau, 3, 2, p_embn+(size_t)NQK*DS, p_clist+2*NC*TOK, p_ccount+2*NC, p_seg);
  dawn_gateC<64><<<TOK,256>>>(p_seg, p_top8+2*TOK*KC, p_idsV, p_valsV, p_cntV, p_nfreqV);
  dawn_emit<<<TOK,256>>>(p_h1, v_neurons, p_idsV, p_valsV, p_cntV, NA_QKV, p_V, nullptr);

  // attention + output projection + residual
  dawn_attn<<<dim3(16,64),256,ATTN_SMEM>>>(p_Q, p_K, p_V, p_attnpre);
  dawn_sgemm<false,true><<<dim3(8,32),256>>>(p_attnpre, expand_O, nullptr, x, p_x2, TOK, DM, DM);

  // knowledge path
  dawn_ln<<<TOK,256>>>(p_x2, ln2s, ln2b, p_h2, 0);
  dawn_sgemm<true,false><<<dim3(1,32),256>>>(p_h2, proj_know_k, proj_know_b, nullptr, p_hknow, TOK, DS, DM);
  dawn_tau<<<TOK,256>>>(p_h2, tau_know_k, tau_know_b, p_tauknow, 1);

  dawn_gateA<<<TOK,256>>>(p_hknow, DS, 0, p_ceknow, p_cfreq+192, p_top8+3*TOK*KC, p_ccount+3*NC, p_clist+3*NC*TOK);
  dawn_gateB<128><<<dim3(64,NC,2),256,GATEB_SMEM>>>(p_hknow, DS, 0, p_tauknow, 1, 0, p_embn+(size_t)(NQK+NV)*DS, p_clist+3*NC*TOK, p_ccount+3*NC, p_seg);
  dawn_gateC<128><<<TOK,256>>>(p_seg, p_top8+3*TOK*KC, p_idsKn, p_valsKn, p_cntKn, p_nfreqKn);
  dawn_emit<<<TOK,256>>>(p_h2, know_neurons, p_idsKn, p_valsKn, p_cntKn, NA_KNOW, out, p_x2);

  dawn_aux<<<1,256>>>(out, out_size);
}

// round 9
// speedup vs baseline: 1.1380x; 1.1380x over previous
#include <cuda_runtime.h>
#include <math.h>

#define BB 4
#define SS 1024
#define TOK (BB*SS)
#define DM 1024
#define DS 128
#define NQK 4096
#define NV 4096
#define NKNOW 8192
#define NC 64
#define KC 8
#define MAXK 128
#define DHEAD 64
#define NA_QKV 512
#define NA_KNOW 1024

__device__ float g_embn[(NQK+NV+NKNOW)*DS];
__device__ float g_ceqk[NC*DS];
__device__ float g_cev[NC*DS];
__device__ float g_ceknow[NC*DS];
__device__ float g_h1[TOK*DM];
__device__ float g_hall[TOK*3*DS];
__device__ float g_tau[TOK*3];
__device__ float g_tauknow[TOK];
__device__ float g_Q[TOK*DM];
__device__ float g_K[TOK*DM];
__device__ float g_V[TOK*DM];
__device__ float g_attnpre[TOK*DM];
__device__ float g_x2[TOK*DM];
__device__ float g_h2[TOK*DM];
__device__ float g_hknow[TOK*DS];
__device__ int   g_idsQ[TOK*NA_QKV];
__device__ int   g_idsK[TOK*NA_QKV];
__device__ int   g_idsV[TOK*NA_QKV];
__device__ int   g_idsKn[TOK*NA_KNOW];
__device__ float g_valsQ[TOK*NA_QKV];
__device__ float g_valsK[TOK*NA_QKV];
__device__ float g_valsV[TOK*NA_QKV];
__device__ float g_valsKn[TOK*NA_KNOW];
__device__ int   g_cntQ[TOK];
__device__ int   g_cntK[TOK];
__device__ int   g_cntV[TOK];
__device__ int   g_cntKn[TOK];
__device__ float g_cfreq[4*NC];
__device__ float g_nfreqQ[NQK];
__device__ float g_nfreqK[NQK];
__device__ float g_nfreqV[NV];
__device__ float g_nfreqKn[NKNOW];
__device__ int   g_ccount[4*NC];
__device__ int   g_clist[4*NC*TOK];
__device__ int   g_top8[4*TOK*KC];
__device__ float g_seg[(size_t)TOK*NA_KNOW];

__device__ __forceinline__ float warp_sum(float v){
#pragma unroll
  for (int o=16;o;o>>=1) v += __shfl_xor_sync(0xffffffffu, v, o);
  return v;
}
__device__ __forceinline__ float warp_max(float v){
#pragma unroll
  for (int o=16;o;o>>=1) v = fmaxf(v, __shfl_xor_sync(0xffffffffu, v, o));
  return v;
}
__device__ __forceinline__ float block_sum(float v, float* s){
  v = warp_sum(v);
  int w = threadIdx.x>>5, l = threadIdx.x&31;
  if (l==0) s[w]=v;
  __syncthreads();
  if (w==0){ float r=(l<8)?s[l]:0.f; r=warp_sum(r); if(l==0) s[0]=r; }
  __syncthreads();
  float r=s[0]; __syncthreads(); return r;
}
__device__ __forceinline__ float block_max(float v, float* s){
  v = warp_max(v);
  int w = threadIdx.x>>5, l = threadIdx.x&31;
  if (l==0) s[w]=v;
  __syncthreads();
  if (w==0){ float r=(l<8)?s[l]:-3.4e38f; r=warp_max(r); if(l==0) s[0]=r; }
  __syncthreads();
  float r=s[0]; __syncthreads(); return r;
}

__global__ __launch_bounds__(256) void dawn_ln(const float* __restrict__ x,
                                               const float* __restrict__ sc,
                                               const float* __restrict__ bi,
                                               float* __restrict__ out, int dozero){
  int t = blockIdx.x, tid = threadIdx.x;
  if (dozero){
    int f = t*256 + tid;
    if (f < 256) g_cfreq[f]=0.f;
    else if (f < 4352) g_nfreqQ[f-256]=0.f;
    else if (f < 8448) g_nfreqK[f-4352]=0.f;
    else if (f < 12544) g_nfreqV[f-8448]=0.f;
    else if (f < 20736) g_nfreqKn[f-12544]=0.f;
    else if (f < 20992) g_ccount[f-20736]=0;
  }
  __shared__ float sred[32];
  float4 xv = ((const float4*)(x + (size_t)t*DM))[tid];
  float mean = block_sum(xv.x+xv.y+xv.z+xv.w, sred) * (1.f/DM);
  float dx=xv.x-mean, dy=xv.y-mean, dz=xv.z-mean, dw=xv.w-mean;
  float var = block_sum(dx*dx+dy*dy+dz*dz+dw*dw, sred) * (1.f/DM);
  float inv = rsqrtf(var + 1e-6f);
  float4 s4 = ((const float4*)sc)[tid];
  float4 b4 = ((const float4*)bi)[tid];
  float4 o; o.x=dx*inv*s4.x+b4.x; o.y=dy*inv*s4.y+b4.y;
  o.z=dz*inv*s4.z+b4.z; o.w=dw*inv*s4.w+b4.w;
  ((float4*)(out + (size_t)t*DM))[tid] = o;
}

__global__ __launch_bounds__(256) void dawn_normall(const float* __restrict__ emb,
                                                    const float* __restrict__ c0,
                                                    const float* __restrict__ c1,
                                                    const float* __restrict__ c2){
  int row = blockIdx.x*8 + (threadIdx.x>>5);
  int lane = threadIdx.x & 31;
  const float* src; float* dst;
  if (row < NQK+NV+NKNOW){ src = emb + (size_t)row*DS; dst = g_embn + (size_t)row*DS; }
  else {
    int r = row - (NQK+NV+NKNOW);
    if (r < NC){ src = c0 + r*DS; dst = g_ceqk + r*DS; }
    else if (r < 2*NC){ src = c1 + (r-NC)*DS; dst = g_cev + (r-NC)*DS; }
    else if (r < 3*NC){ src = c2 + (r-2*NC)*DS; dst = g_ceknow + (r-2*NC)*DS; }
    else return;
  }
  float4 v = ((const float4*)src)[lane];
  float s = warp_sum(v.x*v.x+v.y*v.y+v.z*v.z+v.w*v.w);
  float inv = 1.f/(sqrtf(s)+1e-8f);
  float4 o; o.x=v.x*inv; o.y=v.y*inv; o.z=v.z*inv; o.w=v.w*inv;
  ((float4*)dst)[lane] = o;
}

// 128x64 tile, 8x4 micro, K step 16  (R5 known-good: 80 regs, 33% fma)
template<bool BIAS, bool RES>
__global__ __launch_bounds__(256) void dawn_sgemm(const float* __restrict__ A,
                                                  const float* __restrict__ B,
                                                  const float* __restrict__ bias,
                                                  const float* __restrict__ R,
                                                  float* __restrict__ C,
                                                  int M, int N, int K){
  __shared__ __align__(16) float As[16][136];
  __shared__ __align__(16) float Bs[16][68];
  int mb = blockIdx.y*128, nb = blockIdx.x*64;
  int tid = threadIdx.x;
  int tm = (tid>>4)<<3, tn = (tid&15)<<2;
  float acc[8][4];
#pragma unroll
  for (int i=0;i<8;i++)
#pragma unroll
    for (int j=0;j<4;j++) acc[i][j]=0.f;
  int ar = tid>>1, ac = (tid&1)<<3;
  int bk = tid>>4, bn = (tid&15)<<2;
  for (int k0=0;k0<K;k0+=16){
    float4 a0 = *(const float4*)(A + (size_t)(mb+ar)*K + k0 + ac);
    float4 a1 = *(const float4*)(A + (size_t)(mb+ar)*K + k0 + ac + 4);
    As[ac+0][ar]=a0.x; As[ac+1][ar]=a0.y; As[ac+2][ar]=a0.z; As[ac+3][ar]=a0.w;
    As[ac+4][ar]=a1.x; As[ac+5][ar]=a1.y; As[ac+6][ar]=a1.z; As[ac+7][ar]=a1.w;
    *(float4*)(&Bs[bk][bn]) = *(const float4*)(B + (size_t)(k0+bk)*N + nb + bn);
    __syncthreads();
#pragma unroll
    for (int k=0;k<16;k++){
      float4 av0 = *(const float4*)(&As[k][tm]);
      float4 av1 = *(const float4*)(&As[k][tm+4]);
      float4 bv  = *(const float4*)(&Bs[k][tn]);
      acc[0][0]+=av0.x*bv.x; acc[0][1]+=av0.x*bv.y; acc[0][2]+=av0.x*bv.z; acc[0][3]+=av0.x*bv.w;
      acc[1][0]+=av0.y*bv.x; acc[1][1]+=av0.y*bv.y; acc[1][2]+=av0.y*bv.z; acc[1][3]+=av0.y*bv.w;
      acc[2][0]+=av0.z*bv.x; acc[2][1]+=av0.z*bv.y; acc[2][2]+=av0.z*bv.z; acc[2][3]+=av0.z*bv.w;
      acc[3][0]+=av0.w*bv.x; acc[3][1]+=av0.w*bv.y; acc[3][2]+=av0.w*bv.z; acc[3][3]+=av0.w*bv.w;
      acc[4][0]+=av1.x*bv.x; acc[4][1]+=av1.x*bv.y; acc[4][2]+=av1.x*bv.z; acc[4][3]+=av1.x*bv.w;
      acc[5][0]+=av1.y*bv.x; acc[5][1]+=av1.y*bv.y; acc[5][2]+=av1.y*bv.z; acc[5][3]+=av1.y*bv.w;
      acc[6][0]+=av1.z*bv.x; acc[6][1]+=av1.z*bv.y; acc[6][2]+=av1.z*bv.z; acc[6][3]+=av1.z*bv.w;
      acc[7][0]+=av1.w*bv.x; acc[7][1]+=av1.w*bv.y; acc[7][2]+=av1.w*bv.z; acc[7][3]+=av1.w*bv.w;
    }
    __syncthreads();
  }
#pragma unroll
  for (int i=0;i<8;i++){
    size_t off = (size_t)(mb+tm+i)*N + nb + tn;
    float4 v;
    v.x=acc[i][0]; v.y=acc[i][1]; v.z=acc[i][2]; v.w=acc[i][3];
    if (BIAS){
      const float4 b4 = *(const float4*)(bias + nb + tn);
      v.x+=b4.x; v.y+=b4.y; v.z+=b4.z; v.w+=b4.w;
    }
    if (RES){
      const float4 r4 = *(const float4*)(R + off);
      v.x+=r4.x; v.y+=r4.y; v.z+=r4.z; v.w+=r4.w;
    }
    *(float4*)(C + off) = v;
  }
}

__global__ __launch_bounds__(256) void dawn_tau(const float* __restrict__ h,
                                                const float* __restrict__ W,
                                                const float* __restrict__ bias,
                                                float* __restrict__ out, int ncols){
  int t = blockIdx.x, tid = threadIdx.x;
  float p[3] = {0.f,0.f,0.f};
  const float* row = h + (size_t)t*DM;
  for (int d=tid; d<DM; d+=256){
    float xv = row[d];
    for (int j=0;j<ncols;j++) p[j] += xv * W[d*ncols+j];
  }
  __shared__ float sred[24];
  int w = tid>>5, l = tid&31;
  for (int j=0;j<ncols;j++){
    float s = warp_sum(p[j]);
    if (l==0) sred[w*3+j]=s;
  }
  __syncthreads();
  if (tid < ncols){
    float s=0.f;
    for (int ww=0;ww<8;ww++) s += sred[ww*3+tid];
    out[(size_t)t*ncols+tid] = s + bias[tid];
  }
}

__global__ __launch_bounds__(256) void dawn_gateA(
    const float* __restrict__ hsrc, int hstride, int hoff,
    const float* __restrict__ ce, float* __restrict__ cfreq,
    int* __restrict__ top8, int* __restrict__ ccount, int* __restrict__ clist){
  const int t = blockIdx.x, tid = threadIdx.x;
  const int warp = tid>>5, lane = tid&31;
  __shared__ __align__(16) float sh[DS];
  __shared__ float sc[NC];
  __shared__ int stop8[KC];
  if (tid < DS) sh[tid] = hsrc[(size_t)t*hstride + hoff + tid];
  __syncthreads();
  for (int c = warp*8; c < warp*8+8; ++c){
    const float* cr = ce + c*DS;
    float p = sh[lane]*cr[lane] + sh[lane+32]*cr[lane+32]
            + sh[lane+64]*cr[lane+64] + sh[lane+96]*cr[lane+96];
    p = warp_sum(p);
    if (lane==0) sc[c]=p;
  }
  __syncthreads();
  if (warp==0){
    float v0=sc[lane], v1=sc[lane+32];
    float m = warp_max(fmaxf(v0,v1));
    float e0=expf(v0-m), e1=expf(v1-m);
    float inv = 1.f/warp_sum(e0+e1);
    atomicAdd(&cfreq[lane],    e0*inv);
    atomicAdd(&cfreq[lane+32], e1*inv);
    float a0=v0, a1=v1;
    for (int it=0; it<KC; ++it){
      float mv; int mi;
      if (a0>=a1){ mv=a0; mi=lane; } else { mv=a1; mi=lane+32; }
#pragma unroll
      for (int o=16;o;o>>=1){
        float ov = __shfl_xor_sync(0xffffffffu, mv, o);
        int   oi = __shfl_xor_sync(0xffffffffu, mi, o);
        if (ov>mv || (ov==mv && oi<mi)){ mv=ov; mi=oi; }
      }
      if (lane==0) stop8[it]=mi;
      mi = __shfl_sync(0xffffffffu, mi, 0);
      if (mi==lane) a0=-3.4e38f;
      else if (mi==lane+32) a1=-3.4e38f;
    }
  }
  __syncthreads();
  if (tid < KC){
    int c = stop8[tid];
    top8[t*KC + tid] = c;
    int pos = atomicAdd(&ccount[c], 1);
    clist[c*TOK + pos] = t | (tid<<16);
  }
}

template<int CS>
__global__ __launch_bounds__(256) void dawn_gateB(
    const float* __restrict__ hsrc, int hstride, int hoff,
    const float* __restrict__ tausrc, int taustride, int tauoff,
    const float* __restrict__ emb,
    const int* __restrict__ clist, const int* __restrict__ ccount,
    float* __restrict__ seg){
  const int NA = CS*KC;
  int c = blockIdx.y, chunk = blockIdx.x, ntile = blockIdx.z;
  int count = ccount[c];
  int t0 = chunk*64;
  if (t0 >= count) return;
  int nTok = count - t0; if (nTok > 64) nTok = 64;
  extern __shared__ __align__(16) float smem[];
  float* hT = smem;
  float* eT = smem + 128*68;
  __shared__ int toks[64]; __shared__ int slots[64]; __shared__ float taus[64];
  int tid = threadIdx.x;
  if (tid < 64){
    if (tid < nTok){
      int e = clist[c*TOK + t0 + tid];
      int t = e & 0xFFFF;
      toks[tid] = t; slots[tid] = e >> 16;
      taus[tid] = tausrc[(size_t)t*taustride + tauoff];
    } else toks[tid] = 0x7FFFFFFF;
  }
  __syncthreads();
  for (int i = tid; i < 64*128; i += 256){
    int tt = i >> 7, k = i & 127;
    float v = 0.f;
    if (tt < nTok) v = hsrc[(size_t)toks[tt]*hstride + hoff + k];
    hT[k*68 + tt] = v;
  }
  const float* ebase = emb + ((size_t)c*CS + ntile*64)*DS;
  for (int i = tid; i < 64*128; i += 256){
    int n = i >> 7, k = i & 127;
    eT[k*68 + n] = ebase[(size_t)n*DS + k];
  }
  __syncthreads();
  int tt0 = (tid>>4)<<2, tn0 = (tid&15)<<2;
  float acc[4][4];
#pragma unroll
  for (int a=0;a<4;a++)
#pragma unroll
    for (int b=0;b<4;b++) acc[a][b]=0.f;
#pragma unroll 4
  for (int k=0;k<128;k++){
    float4 hv = *(const float4*)(hT + k*68 + tt0);
    float4 ev = *(const float4*)(eT + k*68 + tn0);
    acc[0][0]+=hv.x*ev.x; acc[0][1]+=hv.x*ev.y; acc[0][2]+=hv.x*ev.z; acc[0][3]+=hv.x*ev.w;
    acc[1][0]+=hv.y*ev.x; acc[1][1]+=hv.y*ev.y; acc[1][2]+=hv.y*ev.z; acc[1][3]+=hv.y*ev.w;
    acc[2][0]+=hv.z*ev.x; acc[2][1]+=hv.z*ev.y; acc[2][2]+=hv.z*ev.z; acc[2][3]+=hv.z*ev.w;
    acc[3][0]+=hv.w*ev.x; acc[3][1]+=hv.w*ev.y; acc[3][2]+=hv.w*ev.z; acc[3][3]+=hv.w*ev.w;
  }
#pragma unroll
  for (int a=0;a<4;a++){
    int j = tt0 + a;
    if (j >= nTok) break;
    float tau = taus[j];
    size_t base = (size_t)toks[j]*NA + (size_t)slots[j]*CS + ntile*64 + tn0;
#pragma unroll
    for (int b=0;b<4;b++){
      float raw = acc[a][b] - tau;
      float e;
      if (raw > 0.f)        e = expf(raw) - 1.0f;
      else if (raw < -5.f)  e = 0.f;
      else {
        float gate = 1e-8f*expf(raw);
        e = expf(gate) - 1.0f;
      }
      seg[base + b] = e;
    }
  }
}

template<int CS>
__global__ __launch_bounds__(256) void dawn_gateC(
    const float* __restrict__ seg_g, const int* __restrict__ top8,
    int* __restrict__ ids, float* __restrict__ vals, int* __restrict__ cnt,
    float* __restrict__ nfreq){
  const int NA = CS*KC;
  const int t = blockIdx.x, tid = threadIdx.x;
  const int warp = tid>>5, lane = tid&31;
  __shared__ float seg[CS*KC];
  __shared__ int stop8[KC];
  __shared__ float sred[32];
  __shared__ int hist[256];
  __shared__ int sfx[257];
  __shared__ int wtot[8];
  __shared__ unsigned s_prefix;
  __shared__ int s_remaining;
  __shared__ int scnt;
  if (tid < KC) stop8[tid] = top8[t*KC + tid];
  if (tid == 0){ scnt=0; s_prefix=0u; s_remaining=MAXK; }
  for (int i=tid;i<NA;i+=256) seg[i] = seg_g[(size_t)t*NA + i];
  __syncthreads();
  for (int pass=3; pass>=0; --pass){
    hist[tid]=0;
    __syncthreads();
    unsigned maskKnown = (pass==3)?0u:(0xFFFFFFFFu << ((pass+1)*8));
    unsigned pfx = s_prefix;
    for (int i=tid;i<NA;i+=256){
      unsigned key = __float_as_uint(seg[i]);
      if ((key & maskKnown) == pfx)
        atomicAdd(&hist[(key >> (pass*8)) & 255], 1);
    }
    __syncthreads();
    int v = hist[255 - tid];
    int sc2 = v;
#pragma unroll
    for (int o=1;o<32;o<<=1){ int t2=__shfl_up_sync(0xffffffffu, sc2, o); if (lane>=o) sc2+=t2; }
    if (lane==31) wtot[warp]=sc2;
    __syncthreads();
    int off=0;
    for (int j=0;j<warp;j++) off+=wtot[j];
    sfx[255 - tid] = sc2 + off;
    if (tid==0) sfx[256]=0;
    __syncthreads();
    int rem = s_remaining;
    if (sfx[tid] >= rem && sfx[tid+1] < rem){
      s_prefix = pfx | ((unsigned)tid << (pass*8));
      s_remaining = rem - sfx[tid+1];
    }
    __syncthreads();
  }
  float thr = __uint_as_float(s_prefix);
  float ps=0.f, pm=0.f;
  for (int i=tid;i<NA;i+=256){
    float e = seg[i];
    if (e >= thr) ps += e;
    pm = fmaxf(pm, e);
  }
  float tot = block_sum(ps, sred);
  float mx  = block_max(pm, sred);
  float scale = tanhf(mx) / (tot + 1e-8f);
  for (int i=tid;i<NA;i+=256){
    float e = seg[i];
    if (e >= thr && e > 0.f){
      int pos = atomicAdd(&scnt, 1);
      int nid = stop8[i/CS]*CS + (i%CS);
      float v = e*scale;
      ids[(size_t)t*NA+pos]  = nid;
      vals[(size_t)t*NA+pos] = v;
      atomicAdd(&nfreq[nid], v);
    }
  }
  __syncthreads();
  if (tid==0) cnt[t]=scnt;
}

// warp-per-neuron emit (R5 known-good)
__global__ __launch_bounds__(256) void dawn_emit(const float* __restrict__ h,
                                                 const float* __restrict__ W,
                                                 const int* __restrict__ idsA,
                                                 const float* __restrict__ valsA,
                                                 const int* __restrict__ cntA,
                                                 int cap,
                                                 float* __restrict__ out,
                                                 const float* __restrict__ resid){
  int t = blockIdx.x, tid = threadIdx.x;
  int w = tid>>5, lane = tid&31;
  __shared__ __align__(16) float sacc[8*DM];
  const int* ids = idsA + (size_t)t*cap;
  const float* vals = valsA + (size_t)t*cap;
  int n = cntA[t];
  float4 h4[8];
  const float4* hrow = (const float4*)(h + (size_t)t*DM);
#pragma unroll
  for (int j=0;j<8;j++) h4[j] = hrow[lane + 32*j];
  float4 acc[8];
#pragma unroll
  for (int j=0;j<8;j++) acc[j] = make_float4(0.f,0.f,0.f,0.f);
  for (int i=w; i<n; i+=8){
    int nid = ids[i];
    float val = vals[i];
    const float4* Wr = (const float4*)(W + (size_t)nid*DM);
    float4 r[8];
#pragma unroll
    for (int j=0;j<8;j++) r[j] = Wr[lane + 32*j];
    float p = 0.f;
#pragma unroll
    for (int j=0;j<8;j++)
      p += r[j].x*h4[j].x + r[j].y*h4[j].y + r[j].z*h4[j].z + r[j].w*h4[j].w;
    p = warp_sum(p);
    float a = p*val;
#pragma unroll
    for (int j=0;j<8;j++){
      acc[j].x += a*r[j].x; acc[j].y += a*r[j].y;
      acc[j].z += a*r[j].z; acc[j].w += a*r[j].w;
    }
  }
  float4* s4 = (float4*)sacc;
#pragma unroll
  for (int j=0;j<8;j++) s4[w*256 + lane + 32*j] = acc[j];
  __syncthreads();
  float4 o = s4[tid];
#pragma unroll
  for (int ww=1; ww<8; ww++){
    float4 v = s4[ww*256 + tid];
    o.x+=v.x; o.y+=v.y; o.z+=v.z; o.w+=v.w;
  }
  if (resid){
    float4 r = ((const float4*)(resid + (size_t)t*DM))[tid];
    o.x+=r.x; o.y+=r.y; o.z+=r.z; o.w+=r.w;
  }
  ((float4*)(out + (size_t)t*DM))[tid] = o;
}

#define ATTN_SMEM (4*64*68*4)
__global__ __launch_bounds__(256) void dawn_attn(const float* __restrict__ Q,
                                                 const float* __restrict__ K,
                                                 const float* __restrict__ V,
                                                 float* __restrict__ O){
  extern __shared__ __align__(16) float smem[];
  float* Qs = smem;
  float* Ks = Qs + 64*68;
  float* Vs = Ks + 64*68;
  float* Ps = Vs + 64*68;
  // LPT scheduling: heaviest q-tiles (most kt iterations) launch first
  int qt = 15 - blockIdx.x;
  int bh = blockIdx.y;
  int b = bh>>4, h = bh&15;
  int tid = threadIdx.x, warp = tid>>5, lane = tid&31;
  size_t tok0 = (size_t)b*SS;
  int qbase = qt*64;
  for (int e=tid; e<64*64; e+=256){
    int r=e>>6, d=e&63;
    Qs[r*68+d] = Q[(tok0 + qbase + r)*DM + h*DHEAD + d] * 0.125f;
  }
  float Oa[8][2], m[8], l[8];
#pragma unroll
  for (int i=0;i<8;i++){ Oa[i][0]=0.f; Oa[i][1]=0.f; m[i]=-3.4e38f; l[i]=0.f; }
  int c0 = lane, c1 = lane+32;
  for (int kt=0; kt<=qt; ++kt){
    __syncthreads();
    for (int e=tid; e<64*64; e+=256){
      int r=e>>6, d=e&63;
      Ks[r*68+d] = K[(tok0 + kt*64 + r)*DM + h*DHEAD + d];
      Vs[r*68+d] = V[(tok0 + kt*64 + r)*DM + h*DHEAD + d];
    }
    __syncthreads();
#pragma unroll
    for (int qr=0;qr<8;qr++){
      int row = warp*8+qr;
      float s0=0.f, s1=0.f;
#pragma unroll
      for (int d4=0; d4<16; d4++){
        float4 qv = *(const float4*)(Qs + row*68 + d4*4);
        float4 k0 = *(const float4*)(Ks + c0*68 + d4*4);
        float4 k1 = *(const float4*)(Ks + c1*68 + d4*4);
        s0 += qv.x*k0.x + qv.y*k0.y + qv.z*k0.z + qv.w*k0.w;
        s1 += qv.x*k1.x + qv.y*k1.y + qv.z*k1.z + qv.w*k1.w;
      }
      int qg = qbase + row;
      if (kt*64 + c0 > qg) s0 = -3.4e38f;
      if (kt*64 + c1 > qg) s1 = -3.4e38f;
      float tm = warp_max(fmaxf(s0,s1));
      float mn = fmaxf(m[qr], tm);
      float corr = __expf(m[qr]-mn);
      float p0 = __expf(s0-mn), p1 = __expf(s1-mn);
      float rs = warp_sum(p0+p1);
      l[qr] = l[qr]*corr + rs;
      m[qr] = mn;
      Oa[qr][0]*=corr; Oa[qr][1]*=corr;
      Ps[row*68+c0]=p0; Ps[row*68+c1]=p1;
    }
    __syncwarp();
#pragma unroll
    for (int k4=0;k4<16;k4++){
      float vv0[4], vv1[4];
#pragma unroll
      for (int kk=0;kk<4;kk++){
        vv0[kk]=Vs[(k4*4+kk)*68+c0];
        vv1[kk]=Vs[(k4*4+kk)*68+c1];
      }
#pragma unroll
      for (int qr=0;qr<8;qr++){
        float4 pv = *(const float4*)(Ps + (warp*8+qr)*68 + k4*4);
        Oa[qr][0] += pv.x*vv0[0] + pv.y*vv0[1] + pv.z*vv0[2] + pv.w*vv0[3];
        Oa[qr][1] += pv.x*vv1[0] + pv.y*vv1[1] + pv.z*vv1[2] + pv.w*vv1[3];
      }
    }
  }
  __syncthreads();
#pragma unroll
  for (int qr=0;qr<8;qr++){
    int row = warp*8+qr;
    float invl = 1.f/l[qr];
    Ps[row*68+c0]=Oa[qr][0]*invl;
    Ps[row*68+c1]=Oa[qr][1]*invl;
  }
  __syncthreads();
  for (int e=tid;e<64*64;e+=256){
    int r=e>>6, d=e&63;
    O[(tok0 + qbase + r)*DM + h*DHEAD + d] = Ps[r*68+d];
  }
}

__global__ __launch_bounds__(256) void dawn_aux(float* __restrict__ out, int out_size){
  if (out_size <= TOK*DM) return;
  int tid = threadIdx.x;
  __shared__ float sred[32];
  float a = 0.f;
  const float invT = 1.f/(float)TOK;
  for (int i=tid;i<4*NC;i+=256){
    float d = g_cfreq[i]*invT - 1.f/(float)NC;
    a += d*d*(float)NC;
  }
  for (int i=tid;i<NQK;i+=256){
    float d;
    d = g_nfreqQ[i]*invT - 1.f/(float)NQK; a += d*d*(float)NQK;
    d = g_nfreqK[i]*invT - 1.f/(float)NQK; a += d*d*(float)NQK;
    d = g_nfreqV[i]*invT - 1.f/(float)NV;  a += d*d*(float)NV;
  }
  for (int i=tid;i<NKNOW;i+=256){
    float d = g_nfreqKn[i]*invT - 1.f/(float)NKNOW;
    a += d*d*(float)NKNOW;
  }
  float tot = block_sum(a, sred);
  if (tid==0) out[TOK*DM] = tot;
}

#define GATEB_SMEM (2*128*68*4)

extern "C" void kernel_launch(void* const* d_in, const int* in_sizes, int n_in,
                              void* d_out, int out_size){
  const float* x           = (const float*)d_in[0];
  const float* neuron_emb  = (const float*)d_in[1];
  const float* proj_attn_k = (const float*)d_in[2];
  const float* proj_attn_b = (const float*)d_in[3];
  const float* tau_attn_k  = (const float*)d_in[4];
  const float* tau_attn_b  = (const float*)d_in[5];
  const float* proj_know_k = (const float*)d_in[6];
  const float* proj_know_b = (const float*)d_in[7];
  const float* tau_know_k  = (const float*)d_in[8];
  const float* tau_know_b  = (const float*)d_in[9];
  const float* ce_qk       = (const float*)d_in[10];
  const float* ce_v        = (const float*)d_in[11];
  const float* ce_know     = (const float*)d_in[12];
  const float* qk_neurons  = (const float*)d_in[13];
  const float* v_neurons   = (const float*)d_in[14];
  const float* know_neurons= (const float*)d_in[15];
  const float* expand_O    = (const float*)d_in[16];
  const float* ln1s = (const float*)d_in[17];
  const float* ln1b = (const float*)d_in[18];
  const float* ln2s = (const float*)d_in[19];
  const float* ln2b = (const float*)d_in[20];
  float* out = (float*)d_out;

  static bool attr_done = false;
  if (!attr_done){
    cudaFuncSetAttribute(dawn_attn, cudaFuncAttributeMaxDynamicSharedMemorySize, ATTN_SMEM);
    cudaFuncSetAttribute(dawn_gateB<64>,  cudaFuncAttributeMaxDynamicSharedMemorySize, GATEB_SMEM);
    cudaFuncSetAttribute(dawn_gateB<128>, cudaFuncAttributeMaxDynamicSharedMemorySize, GATEB_SMEM);
    attr_done = true;
  }

  float *p_embn,*p_ceqk,*p_cev,*p_ceknow,*p_h1,*p_hall,*p_tau,*p_tauknow;
  float *p_Q,*p_K,*p_V,*p_attnpre,*p_x2,*p_h2,*p_hknow,*p_seg;
  int *p_idsQ,*p_idsK,*p_idsV,*p_idsKn,*p_cntQ,*p_cntK,*p_cntV,*p_cntKn;
  int *p_ccount,*p_clist,*p_top8;
  float *p_valsQ,*p_valsK,*p_valsV,*p_valsKn,*p_cfreq,*p_nfreqQ,*p_nfreqK,*p_nfreqV,*p_nfreqKn;
  cudaGetSymbolAddress((void**)&p_embn, g_embn);
  cudaGetSymbolAddress((void**)&p_ceqk, g_ceqk);
  cudaGetSymbolAddress((void**)&p_cev, g_cev);
  cudaGetSymbolAddress((void**)&p_ceknow, g_ceknow);
  cudaGetSymbolAddress((void**)&p_h1, g_h1);
  cudaGetSymbolAddress((void**)&p_hall, g_hall);
  cudaGetSymbolAddress((void**)&p_tau, g_tau);
  cudaGetSymbolAddress((void**)&p_tauknow, g_tauknow);
  cudaGetSymbolAddress((void**)&p_Q, g_Q);
  cudaGetSymbolAddress((void**)&p_K, g_K);
  cudaGetSymbolAddress((void**)&p_V, g_V);
  cudaGetSymbolAddress((void**)&p_attnpre, g_attnpre);
  cudaGetSymbolAddress((void**)&p_x2, g_x2);
  cudaGetSymbolAddress((void**)&p_h2, g_h2);
  cudaGetSymbolAddress((void**)&p_hknow, g_hknow);
  cudaGetSymbolAddress((void**)&p_seg, g_seg);
  cudaGetSymbolAddress((void**)&p_idsQ, g_idsQ);
  cudaGetSymbolAddress((void**)&p_idsK, g_idsK);
  cudaGetSymbolAddress((void**)&p_idsV, g_idsV);
  cudaGetSymbolAddress((void**)&p_idsKn, g_idsKn);
  cudaGetSymbolAddress((void**)&p_valsQ, g_valsQ);
  cudaGetSymbolAddress((void**)&p_valsK, g_valsK);
  cudaGetSymbolAddress((void**)&p_valsV, g_valsV);
  cudaGetSymbolAddress((void**)&p_valsKn, g_valsKn);
  cudaGetSymbolAddress((void**)&p_cntQ, g_cntQ);
  cudaGetSymbolAddress((void**)&p_cntK, g_cntK);
  cudaGetSymbolAddress((void**)&p_cntV, g_cntV);
  cudaGetSymbolAddress((void**)&p_cntKn, g_cntKn);
  cudaGetSymbolAddress((void**)&p_cfreq, g_cfreq);
  cudaGetSymbolAddress((void**)&p_nfreqQ, g_nfreqQ);
  cudaGetSymbolAddress((void**)&p_nfreqK, g_nfreqK);
  cudaGetSymbolAddress((void**)&p_nfreqV, g_nfreqV);
  cudaGetSymbolAddress((void**)&p_nfreqKn, g_nfreqKn);
  cudaGetSymbolAddress((void**)&p_ccount, g_ccount);
  cudaGetSymbolAddress((void**)&p_clist, g_clist);
  cudaGetSymbolAddress((void**)&p_top8, g_top8);

  // 1: LN1 (+ zero scratch)   2: tau   3: row-normalize   4: proj GEMM (profiled)
  dawn_ln<<<TOK,256>>>(x, ln1s, ln1b, p_h1, 1);
  dawn_tau<<<TOK,256>>>(p_h1, tau_attn_k, tau_attn_b, p_tau, 3);
  dawn_normall<<<(NQK+NV+NKNOW+3*NC)/8,256>>>(neuron_emb, ce_qk, ce_v, ce_know);
  dawn_sgemm<true,false><<<dim3(6,32),256>>>(p_h1, proj_attn_k, proj_attn_b, nullptr, p_hall, TOK, 3*DS, DM);

  // Q gate
  dawn_gateA<<<TOK,256>>>(p_hall, 3*DS, 0, p_ceqk, p_cfreq+0, p_top8+0*TOK*KC, p_ccount+0*NC, p_clist+0*NC*TOK);
  dawn_gateB<64><<<dim3(64,NC,1),256,GATEB_SMEM>>>(p_hall, 3*DS, 0, p_tau, 3, 0, p_embn, p_clist+0*NC*TOK, p_ccount+0*NC, p_seg);
  dawn_gateC<64><<<TOK,256>>>(p_seg, p_top8+0*TOK*KC, p_idsQ, p_valsQ, p_cntQ, p_nfreqQ);
  dawn_emit<<<TOK,256>>>(p_h1, qk_neurons, p_idsQ, p_valsQ, p_cntQ, NA_QKV, p_Q, nullptr);

  // K gate
  dawn_gateA<<<TOK,256>>>(p_hall, 3*DS, 128, p_ceqk, p_cfreq+64, p_top8+1*TOK*KC, p_ccount+1*NC, p_clist+1*NC*TOK);
  dawn_gateB<64><<<dim3(64,NC,1),256,GATEB_SMEM>>>(p_hall, 3*DS, 128, p_tau, 3, 1, p_embn, p_clist+1*NC*TOK, p_ccount+1*NC, p_seg);
  dawn_gateC<64><<<TOK,256>>>(p_seg, p_top8+1*TOK*KC, p_idsK, p_valsK, p_cntK, p_nfreqK);
  dawn_emit<<<TOK,256>>>(p_h1, qk_neurons, p_idsK, p_valsK, p_cntK, NA_QKV, p_K, nullptr);

  // V gate
  dawn_gateA<<<TOK,256>>>(p_hall, 3*DS, 256, p_cev, p_cfreq+128, p_top8+2*TOK*KC, p_ccount+2*NC, p_clist+2*NC*TOK);
  dawn_gateB<64><<<dim3(64,NC,1),256,GATEB_SMEM>>>(p_hall, 3*DS, 256, p_tau, 3, 2, p_embn+(size_t)NQK*DS, p_clist+2*NC*TOK, p_ccount+2*NC, p_seg);
  dawn_gateC<64><<<TOK,256>>>(p_seg, p_top8+2*TOK*KC, p_idsV, p_valsV, p_cntV, p_nfreqV);
  dawn_emit<<<TOK,256>>>(p_h1, v_neurons, p_idsV, p_valsV, p_cntV, NA_QKV, p_V, nullptr);

  // attention + output projection + residual
  dawn_attn<<<dim3(16,64),256,ATTN_SMEM>>>(p_Q, p_K, p_V, p_attnpre);
  dawn_sgemm<false,true><<<dim3(16,32),256>>>(p_attnpre, expand_O, nullptr, x, p_x2, TOK, DM, DM);

  // knowledge path
  dawn_ln<<<TOK,256>>>(p_x2, ln2s, ln2b, p_h2, 0);
  dawn_sgemm<true,false><<<dim3(2,32),256>>>(p_h2, proj_know_k, proj_know_b, nullptr, p_hknow, TOK, DS, DM);
  dawn_tau<<<TOK,256>>>(p_h2, tau_know_k, tau_know_b, p_tauknow, 1);

  dawn_gateA<<<TOK,256>>>(p_hknow, DS, 0, p_ceknow, p_cfreq+192, p_top8+3*TOK*KC, p_ccount+3*NC, p_clist+3*NC*TOK);
  dawn_gateB<128><<<dim3(64,NC,2),256,GATEB_SMEM>>>(p_hknow, DS, 0, p_tauknow, 1, 0, p_embn+(size_t)(NQK+NV)*DS, p_clist+3*NC*TOK, p_ccount+3*NC, p_seg);
  dawn_gateC<128><<<TOK,256>>>(p_seg, p_top8+3*TOK*KC, p_idsKn, p_valsKn, p_cntKn, p_nfreqKn);
  dawn_emit<<<TOK,256>>>(p_h2, know_neurons, p_idsKn, p_valsKn, p_cntKn, NA_KNOW, out, p_x2);

  dawn_aux<<<1,256>>>(out, out_size);
}

// round 11
// speedup vs baseline: 1.3185x; 1.1586x over previous
#include <cuda_runtime.h>
#include <cuda_bf16.h>
#include <mma.h>
#include <math.h>
using namespace nvcuda;

#define BB 4
#define SS 1024
#define TOK (BB*SS)
#define DM 1024
#define DS 128
#define NQK 4096
#define NV 4096
#define NKNOW 8192
#define NC 64
#define KC 8
#define MAXK 128
#define DHEAD 64
#define NA_QKV 512
#define NA_KNOW 1024

__device__ float g_embn[(NQK+NV+NKNOW)*DS];
__device__ float g_ceqk[NC*DS];
__device__ float g_cev[NC*DS];
__device__ float g_ceknow[NC*DS];
__device__ float g_h1[TOK*DM];
__device__ float g_hall[TOK*3*DS];
__device__ float g_tau[TOK*3];
__device__ float g_tauknow[TOK];
__device__ float g_Q[TOK*DM];
__device__ float g_K[TOK*DM];
__device__ float g_V[TOK*DM];
__device__ float g_attnpre[TOK*DM];
__device__ float g_x2[TOK*DM];
__device__ float g_h2[TOK*DM];
__device__ float g_hknow[TOK*DS];
__device__ int   g_idsQ[TOK*NA_QKV];
__device__ int   g_idsK[TOK*NA_QKV];
__device__ int   g_idsV[TOK*NA_QKV];
__device__ int   g_idsKn[TOK*NA_KNOW];
__device__ float g_valsQ[TOK*NA_QKV];
__device__ float g_valsK[TOK*NA_QKV];
__device__ float g_valsV[TOK*NA_QKV];
__device__ float g_valsKn[TOK*NA_KNOW];
__device__ int   g_cntQ[TOK];
__device__ int   g_cntK[TOK];
__device__ int   g_cntV[TOK];
__device__ int   g_cntKn[TOK];
__device__ float g_cfreq[4*NC];
__device__ float g_nfreqQ[NQK];
__device__ float g_nfreqK[NQK];
__device__ float g_nfreqV[NV];
__device__ float g_nfreqKn[NKNOW];
__device__ int   g_ccount[4*NC];
__device__ int   g_clist[4*NC*TOK];
__device__ int   g_top8[4*TOK*KC];
__device__ float g_seg[(size_t)TOK*NA_KNOW];

__device__ __forceinline__ float warp_sum(float v){
#pragma unroll
  for (int o=16;o;o>>=1) v += __shfl_xor_sync(0xffffffffu, v, o);
  return v;
}
__device__ __forceinline__ float warp_max(float v){
#pragma unroll
  for (int o=16;o;o>>=1) v = fmaxf(v, __shfl_xor_sync(0xffffffffu, v, o));
  return v;
}
__device__ __forceinline__ float block_sum(float v, float* s){
  v = warp_sum(v);
  int w = threadIdx.x>>5, l = threadIdx.x&31;
  if (l==0) s[w]=v;
  __syncthreads();
  if (w==0){ float r=(l<8)?s[l]:0.f; r=warp_sum(r); if(l==0) s[0]=r; }
  __syncthreads();
  float r=s[0]; __syncthreads(); return r;
}
__device__ __forceinline__ float block_max(float v, float* s){
  v = warp_max(v);
  int w = threadIdx.x>>5, l = threadIdx.x&31;
  if (l==0) s[w]=v;
  __syncthreads();
  if (w==0){ float r=(l<8)?s[l]:-3.4e38f; r=warp_max(r); if(l==0) s[0]=r; }
  __syncthreads();
  float r=s[0]; __syncthreads(); return r;
}

__global__ __launch_bounds__(256) void dawn_ln(const float* __restrict__ x,
                                               const float* __restrict__ sc,
                                               const float* __restrict__ bi,
                                               float* __restrict__ out, int dozero){
  int t = blockIdx.x, tid = threadIdx.x;
  if (dozero){
    int f = t*256 + tid;
    if (f < 256) g_cfreq[f]=0.f;
    else if (f < 4352) g_nfreqQ[f-256]=0.f;
    else if (f < 8448) g_nfreqK[f-4352]=0.f;
    else if (f < 12544) g_nfreqV[f-8448]=0.f;
    else if (f < 20736) g_nfreqKn[f-12544]=0.f;
    else if (f < 20992) g_ccount[f-20736]=0;
  }
  __shared__ float sred[32];
  float4 xv = ((const float4*)(x + (size_t)t*DM))[tid];
  float mean = block_sum(xv.x+xv.y+xv.z+xv.w, sred) * (1.f/DM);
  float dx=xv.x-mean, dy=xv.y-mean, dz=xv.z-mean, dw=xv.w-mean;
  float var = block_sum(dx*dx+dy*dy+dz*dz+dw*dw, sred) * (1.f/DM);
  float inv = rsqrtf(var + 1e-6f);
  float4 s4 = ((const float4*)sc)[tid];
  float4 b4 = ((const float4*)bi)[tid];
  float4 o; o.x=dx*inv*s4.x+b4.x; o.y=dy*inv*s4.y+b4.y;
  o.z=dz*inv*s4.z+b4.z; o.w=dw*inv*s4.w+b4.w;
  ((float4*)(out + (size_t)t*DM))[tid] = o;
}

__global__ __launch_bounds__(256) void dawn_normall(const float* __restrict__ emb,
                                                    const float* __restrict__ c0,
                                                    const float* __restrict__ c1,
                                                    const float* __restrict__ c2){
  int row = blockIdx.x*8 + (threadIdx.x>>5);
  int lane = threadIdx.x & 31;
  const float* src; float* dst;
  if (row < NQK+NV+NKNOW){ src = emb + (size_t)row*DS; dst = g_embn + (size_t)row*DS; }
  else {
    int r = row - (NQK+NV+NKNOW);
    if (r < NC){ src = c0 + r*DS; dst = g_ceqk + r*DS; }
    else if (r < 2*NC){ src = c1 + (r-NC)*DS; dst = g_cev + (r-NC)*DS; }
    else if (r < 3*NC){ src = c2 + (r-2*NC)*DS; dst = g_ceknow + (r-2*NC)*DS; }
    else return;
  }
  float4 v = ((const float4*)src)[lane];
  float s = warp_sum(v.x*v.x+v.y*v.y+v.z*v.z+v.w*v.w);
  float inv = 1.f/(sqrtf(s)+1e-8f);
  float4 o; o.x=v.x*inv; o.y=v.y*inv; o.z=v.z*inv; o.w=v.w*inv;
  ((float4*)dst)[lane] = o;
}

// bf16 tensor-core GEMM: 128x64 tile, K step 32, 8 warps (4x2) x 32x32 each.
// fp32 accumulate; bias/residual in fp32 epilogue.
#define BGM 128
#define BGN 64
#define BGK 32
template<bool BIAS, bool RES>
__global__ __launch_bounds__(256) void dawn_bgemm(const float* __restrict__ A,
                                                  const float* __restrict__ B,
                                                  const float* __restrict__ bias,
                                                  const float* __restrict__ R,
                                                  float* __restrict__ C,
                                                  int M, int N, int K){
  __shared__ __align__(16) __nv_bfloat16 Asm[BGM][BGK+8];
  __shared__ __align__(16) __nv_bfloat16 Bsm[BGK][BGN+8];
  __shared__ __align__(16) float Csm[BGM][BGN];
  int mb = blockIdx.y*BGM, nb = blockIdx.x*BGN;
  int tid = threadIdx.x, warp = tid>>5;
  int wm = (warp & 3) * 32;
  int wn = (warp >> 2) * 32;
  wmma::fragment<wmma::accumulator,16,16,16,float> cf[2][2];
#pragma unroll
  for (int i=0;i<2;i++)
#pragma unroll
    for (int j=0;j<2;j++) wmma::fill_fragment(cf[i][j], 0.f);

  for (int k0=0;k0<K;k0+=BGK){
#pragma unroll
    for (int it=0; it<4; ++it){
      int i = tid + it*256;
      int r = i >> 3, c4 = i & 7;
      float4 v = *(const float4*)(A + (size_t)(mb+r)*K + k0 + c4*4);
      __nv_bfloat162* d = (__nv_bfloat162*)&Asm[r][c4*4];
      d[0] = __floats2bfloat162_rn(v.x, v.y);
      d[1] = __floats2bfloat162_rn(v.z, v.w);
    }
#pragma unroll
    for (int it=0; it<2; ++it){
      int i = tid + it*256;
      int r = i >> 4, c4 = i & 15;
      float4 v = *(const float4*)(B + (size_t)(k0+r)*N + nb + c4*4);
      __nv_bfloat162* d = (__nv_bfloat162*)&Bsm[r][c4*4];
      d[0] = __floats2bfloat162_rn(v.x, v.y);
      d[1] = __floats2bfloat162_rn(v.z, v.w);
    }
    __syncthreads();
#pragma unroll
    for (int kk=0; kk<BGK; kk+=16){
      wmma::fragment<wmma::matrix_a,16,16,16,__nv_bfloat16,wmma::row_major> af[2];
      wmma::fragment<wmma::matrix_b,16,16,16,__nv_bfloat16,wmma::row_major> bf[2];
      wmma::load_matrix_sync(af[0], &Asm[wm][kk],    BGK+8);
      wmma::load_matrix_sync(af[1], &Asm[wm+16][kk], BGK+8);
      wmma::load_matrix_sync(bf[0], &Bsm[kk][wn],    BGN+8);
      wmma::load_matrix_sync(bf[1], &Bsm[kk][wn+16], BGN+8);
#pragma unroll
      for (int i=0;i<2;i++)
#pragma unroll
        for (int j=0;j<2;j++)
          wmma::mma_sync(cf[i][j], af[i], bf[j], cf[i][j]);
    }
    __syncthreads();
  }
#pragma unroll
  for (int i=0;i<2;i++)
#pragma unroll
    for (int j=0;j<2;j++)
      wmma::store_matrix_sync(&Csm[wm+16*i][wn+16*j], cf[i][j], BGN, wmma::mem_row_major);
  __syncthreads();
#pragma unroll
  for (int it=0; it<8; ++it){
    int i = tid + it*256;
    int r = i >> 4, c4 = i & 15;
    float4 v = *(const float4*)(&Csm[r][c4*4]);
    size_t off = (size_t)(mb+r)*N + nb + c4*4;
    if (BIAS){
      const float4 b4 = *(const float4*)(bias + nb + c4*4);
      v.x+=b4.x; v.y+=b4.y; v.z+=b4.z; v.w+=b4.w;
    }
    if (RES){
      const float4 r4 = *(const float4*)(R + off);
      v.x+=r4.x; v.y+=r4.y; v.z+=r4.z; v.w+=r4.w;
    }
    *(float4*)(C + off) = v;
  }
}

__global__ __launch_bounds__(256) void dawn_tau(const float* __restrict__ h,
                                                const float* __restrict__ W,
                                                const float* __restrict__ bias,
                                                float* __restrict__ out, int ncols){
  int t = blockIdx.x, tid = threadIdx.x;
  float p[3] = {0.f,0.f,0.f};
  const float* row = h + (size_t)t*DM;
  for (int d=tid; d<DM; d+=256){
    float xv = row[d];
    for (int j=0;j<ncols;j++) p[j] += xv * W[d*ncols+j];
  }
  __shared__ float sred[24];
  int w = tid>>5, l = tid&31;
  for (int j=0;j<ncols;j++){
    float s = warp_sum(p[j]);
    if (l==0) sred[w*3+j]=s;
  }
  __syncthreads();
  if (tid < ncols){
    float s=0.f;
    for (int ww=0;ww<8;ww++) s += sred[ww*3+tid];
    out[(size_t)t*ncols+tid] = s + bias[tid];
  }
}

__global__ __launch_bounds__(256) void dawn_gateA(
    const float* __restrict__ hsrc, int hstride, int hoff,
    const float* __restrict__ ce, float* __restrict__ cfreq,
    int* __restrict__ top8, int* __restrict__ ccount, int* __restrict__ clist){
  const int t = blockIdx.x, tid = threadIdx.x;
  const int warp = tid>>5, lane = tid&31;
  __shared__ __align__(16) float sh[DS];
  __shared__ float sc[NC];
  __shared__ int stop8[KC];
  if (tid < DS) sh[tid] = hsrc[(size_t)t*hstride + hoff + tid];
  __syncthreads();
  for (int c = warp*8; c < warp*8+8; ++c){
    const float* cr = ce + c*DS;
    float p = sh[lane]*cr[lane] + sh[lane+32]*cr[lane+32]
            + sh[lane+64]*cr[lane+64] + sh[lane+96]*cr[lane+96];
    p = warp_sum(p);
    if (lane==0) sc[c]=p;
  }
  __syncthreads();
  if (warp==0){
    float v0=sc[lane], v1=sc[lane+32];
    float m = warp_max(fmaxf(v0,v1));
    float e0=expf(v0-m), e1=expf(v1-m);
    float inv = 1.f/warp_sum(e0+e1);
    atomicAdd(&cfreq[lane],    e0*inv);
    atomicAdd(&cfreq[lane+32], e1*inv);
    float a0=v0, a1=v1;
    for (int it=0; it<KC; ++it){
      float mv; int mi;
      if (a0>=a1){ mv=a0; mi=lane; } else { mv=a1; mi=lane+32; }
#pragma unroll
      for (int o=16;o;o>>=1){
        float ov = __shfl_xor_sync(0xffffffffu, mv, o);
        int   oi = __shfl_xor_sync(0xffffffffu, mi, o);
        if (ov>mv || (ov==mv && oi<mi)){ mv=ov; mi=oi; }
      }
      if (lane==0) stop8[it]=mi;
      mi = __shfl_sync(0xffffffffu, mi, 0);
      if (mi==lane) a0=-3.4e38f;
      else if (mi==lane+32) a1=-3.4e38f;
    }
  }
  __syncthreads();
  if (tid < KC){
    int c = stop8[tid];
    top8[t*KC + tid] = c;
    int pos = atomicAdd(&ccount[c], 1);
    clist[c*TOK + pos] = t | (tid<<16);
  }
}

template<int CS>
__global__ __launch_bounds__(256) void dawn_gateB(
    const float* __restrict__ hsrc, int hstride, int hoff,
    const float* __restrict__ tausrc, int taustride, int tauoff,
    const float* __restrict__ emb,
    const int* __restrict__ clist, const int* __restrict__ ccount,
    float* __restrict__ seg){
  const int NA = CS*KC;
  int c = blockIdx.y, chunk = blockIdx.x, ntile = blockIdx.z;
  int count = ccount[c];
  int t0 = chunk*64;
  if (t0 >= count) return;
  int nTok = count - t0; if (nTok > 64) nTok = 64;
  extern __shared__ __align__(16) float smem[];
  float* hT = smem;
  float* eT = smem + 128*68;
  __shared__ int toks[64]; __shared__ int slots[64]; __shared__ float taus[64];
  int tid = threadIdx.x;
  if (tid < 64){
    if (tid < nTok){
      int e = clist[c*TOK + t0 + tid];
      int t = e & 0xFFFF;
      toks[tid] = t; slots[tid] = e >> 16;
      taus[tid] = tausrc[(size_t)t*taustride + tauoff];
    } else toks[tid] = 0x7FFFFFFF;
  }
  __syncthreads();
  for (int i = tid; i < 64*128; i += 256){
    int tt = i >> 7, k = i & 127;
    float v = 0.f;
    if (tt < nTok) v = hsrc[(size_t)toks[tt]*hstride + hoff + k];
    hT[k*68 + tt] = v;
  }
  const float* ebase = emb + ((size_t)c*CS + ntile*64)*DS;
  for (int i = tid; i < 64*128; i += 256){
    int n = i >> 7, k = i & 127;
    eT[k*68 + n] = ebase[(size_t)n*DS + k];
  }
  __syncthreads();
  int tt0 = (tid>>4)<<2, tn0 = (tid&15)<<2;
  float acc[4][4];
#pragma unroll
  for (int a=0;a<4;a++)
#pragma unroll
    for (int b=0;b<4;b++) acc[a][b]=0.f;
#pragma unroll 4
  for (int k=0;k<128;k++){
    float4 hv = *(const float4*)(hT + k*68 + tt0);
    float4 ev = *(const float4*)(eT + k*68 + tn0);
    acc[0][0]+=hv.x*ev.x; acc[0][1]+=hv.x*ev.y; acc[0][2]+=hv.x*ev.z; acc[0][3]+=hv.x*ev.w;
    acc[1][0]+=hv.y*ev.x; acc[1][1]+=hv.y*ev.y; acc[1][2]+=hv.y*ev.z; acc[1][3]+=hv.y*ev.w;
    acc[2][0]+=hv.z*ev.x; acc[2][1]+=hv.z*ev.y; acc[2][2]+=hv.z*ev.z; acc[2][3]+=hv.z*ev.w;
    acc[3][0]+=hv.w*ev.x; acc[3][1]+=hv.w*ev.y; acc[3][2]+=hv.w*ev.z; acc[3][3]+=hv.w*ev.w;
  }
#pragma unroll
  for (int a=0;a<4;a++){
    int j = tt0 + a;
    if (j >= nTok) break;
    float tau = taus[j];
    size_t base = (size_t)toks[j]*NA + (size_t)slots[j]*CS + ntile*64 + tn0;
#pragma unroll
    for (int b=0;b<4;b++){
      float raw = acc[a][b] - tau;
      float e;
      if (raw > 0.f)        e = expf(raw) - 1.0f;
      else if (raw < -5.f)  e = 0.f;
      else {
        float gate = 1e-8f*expf(raw);
        e = expf(gate) - 1.0f;
      }
      seg[base + b] = e;
    }
  }
}

template<int CS>
__global__ __launch_bounds__(256) void dawn_gateC(
    const float* __restrict__ seg_g, const int* __restrict__ top8,
    int* __restrict__ ids, float* __restrict__ vals, int* __restrict__ cnt,
    float* __restrict__ nfreq){
  const int NA = CS*KC;
  const int t = blockIdx.x, tid = threadIdx.x;
  const int warp = tid>>5, lane = tid&31;
  __shared__ float seg[CS*KC];
  __shared__ int stop8[KC];
  __shared__ float sred[32];
  __shared__ int hist[256];
  __shared__ int sfx[257];
  __shared__ int wtot[8];
  __shared__ unsigned s_prefix;
  __shared__ int s_remaining;
  __shared__ int scnt;
  if (tid < KC) stop8[tid] = top8[t*KC + tid];
  if (tid == 0){ scnt=0; s_prefix=0u; s_remaining=MAXK; }
  for (int i=tid;i<NA;i+=256) seg[i] = seg_g[(size_t)t*NA + i];
  __syncthreads();
  for (int pass=3; pass>=0; --pass){
    hist[tid]=0;
    __syncthreads();
    unsigned maskKnown = (pass==3)?0u:(0xFFFFFFFFu << ((pass+1)*8));
    unsigned pfx = s_prefix;
    for (int i=tid;i<NA;i+=256){
      unsigned key = __float_as_uint(seg[i]);
      if ((key & maskKnown) == pfx)
        atomicAdd(&hist[(key >> (pass*8)) & 255], 1);
    }
    __syncthreads();
    int v = hist[255 - tid];
    int sc2 = v;
#pragma unroll
    for (int o=1;o<32;o<<=1){ int t2=__shfl_up_sync(0xffffffffu, sc2, o); if (lane>=o) sc2+=t2; }
    if (lane==31) wtot[warp]=sc2;
    __syncthreads();
    int off=0;
    for (int j=0;j<warp;j++) off+=wtot[j];
    sfx[255 - tid] = sc2 + off;
    if (tid==0) sfx[256]=0;
    __syncthreads();
    int rem = s_remaining;
    if (sfx[tid] >= rem && sfx[tid+1] < rem){
      s_prefix = pfx | ((unsigned)tid << (pass*8));
      s_remaining = rem - sfx[tid+1];
    }
    __syncthreads();
  }
  float thr = __uint_as_float(s_prefix);
  float ps=0.f, pm=0.f;
  for (int i=tid;i<NA;i+=256){
    float e = seg[i];
    if (e >= thr) ps += e;
    pm = fmaxf(pm, e);
  }
  float tot = block_sum(ps, sred);
  float mx  = block_max(pm, sred);
  float scale = tanhf(mx) / (tot + 1e-8f);
  for (int i=tid;i<NA;i+=256){
    float e = seg[i];
    if (e >= thr && e > 0.f){
      int pos = atomicAdd(&scnt, 1);
      int nid = stop8[i/CS]*CS + (i%CS);
      float v = e*scale;
      ids[(size_t)t*NA+pos]  = nid;
      vals[(size_t)t*NA+pos] = v;
      atomicAdd(&nfreq[nid], v);
    }
  }
  __syncthreads();
  if (tid==0) cnt[t]=scnt;
}

// warp-per-neuron emit (known-good)
__global__ __launch_bounds__(256) void dawn_emit(const float* __restrict__ h,
                                                 const float* __restrict__ W,
                                                 const int* __restrict__ idsA,
                                                 const float* __restrict__ valsA,
                                                 const int* __restrict__ cntA,
                                                 int cap,
                                                 float* __restrict__ out,
                                                 const float* __restrict__ resid){
  int t = blockIdx.x, tid = threadIdx.x;
  int w = tid>>5, lane = tid&31;
  __shared__ __align__(16) float sacc[8*DM];
  const int* ids = idsA + (size_t)t*cap;
  const float* vals = valsA + (size_t)t*cap;
  int n = cntA[t];
  float4 h4[8];
  const float4* hrow = (const float4*)(h + (size_t)t*DM);
#pragma unroll
  for (int j=0;j<8;j++) h4[j] = hrow[lane + 32*j];
  float4 acc[8];
#pragma unroll
  for (int j=0;j<8;j++) acc[j] = make_float4(0.f,0.f,0.f,0.f);
  for (int i=w; i<n; i+=8){
    int nid = ids[i];
    float val = vals[i];
    const float4* Wr = (const float4*)(W + (size_t)nid*DM);
    float4 r[8];
#pragma unroll
    for (int j=0;j<8;j++) r[j] = Wr[lane + 32*j];
    float p = 0.f;
#pragma unroll
    for (int j=0;j<8;j++)
      p += r[j].x*h4[j].x + r[j].y*h4[j].y + r[j].z*h4[j].z + r[j].w*h4[j].w;
    p = warp_sum(p);
    float a = p*val;
#pragma unroll
    for (int j=0;j<8;j++){
      acc[j].x += a*r[j].x; acc[j].y += a*r[j].y;
      acc[j].z += a*r[j].z; acc[j].w += a*r[j].w;
    }
  }
  float4* s4 = (float4*)sacc;
#pragma unroll
  for (int j=0;j<8;j++) s4[w*256 + lane + 32*j] = acc[j];
  __syncthreads();
  float4 o = s4[tid];
#pragma unroll
  for (int ww=1; ww<8; ww++){
    float4 v = s4[ww*256 + tid];
    o.x+=v.x; o.y+=v.y; o.z+=v.z; o.w+=v.w;
  }
  if (resid){
    float4 r = ((const float4*)(resid + (size_t)t*DM))[tid];
    o.x+=r.x; o.y+=r.y; o.z+=r.z; o.w+=r.w;
  }
  ((float4*)(out + (size_t)t*DM))[tid] = o;
}

#define ATTN_SMEM (4*64*68*4)
__global__ __launch_bounds__(256) void dawn_attn(const float* __restrict__ Q,
                                                 const float* __restrict__ K,
                                                 const float* __restrict__ V,
                                                 float* __restrict__ O){
  extern __shared__ __align__(16) float smem[];
  float* Qs = smem;
  float* Ks = Qs + 64*68;
  float* Vs = Ks + 64*68;
  float* Ps = Vs + 64*68;
  int qt = 15 - blockIdx.x;
  int bh = blockIdx.y;
  int b = bh>>4, h = bh&15;
  int tid = threadIdx.x, warp = tid>>5, lane = tid&31;
  size_t tok0 = (size_t)b*SS;
  int qbase = qt*64;
  for (int e=tid; e<64*64; e+=256){
    int r=e>>6, d=e&63;
    Qs[r*68+d] = Q[(tok0 + qbase + r)*DM + h*DHEAD + d] * 0.125f;
  }
  float Oa[8][2], m[8], l[8];
#pragma unroll
  for (int i=0;i<8;i++){ Oa[i][0]=0.f; Oa[i][1]=0.f; m[i]=-3.4e38f; l[i]=0.f; }
  int c0 = lane, c1 = lane+32;
  for (int kt=0; kt<=qt; ++kt){
    __syncthreads();
    for (int e=tid; e<64*64; e+=256){
      int r=e>>6, d=e&63;
      Ks[r*68+d] = K[(tok0 + kt*64 + r)*DM + h*DHEAD + d];
      Vs[r*68+d] = V[(tok0 + kt*64 + r)*DM + h*DHEAD + d];
    }
    __syncthreads();
#pragma unroll
    for (int qr=0;qr<8;qr++){
      int row = warp*8+qr;
      float s0=0.f, s1=0.f;
#pragma unroll
      for (int d4=0; d4<16; d4++){
        float4 qv = *(const float4*)(Qs + row*68 + d4*4);
        float4 k0 = *(const float4*)(Ks + c0*68 + d4*4);
        float4 k1 = *(const float4*)(Ks + c1*68 + d4*4);
        s0 += qv.x*k0.x + qv.y*k0.y + qv.z*k0.z + qv.w*k0.w;
        s1 += qv.x*k1.x + qv.y*k1.y + qv.z*k1.z + qv.w*k1.w;
      }
      int qg = qbase + row;
      if (kt*64 + c0 > qg) s0 = -3.4e38f;
      if (kt*64 + c1 > qg) s1 = -3.4e38f;
      float tm = warp_max(fmaxf(s0,s1));
      float mn = fmaxf(m[qr], tm);
      float corr = __expf(m[qr]-mn);
      float p0 = __expf(s0-mn), p1 = __expf(s1-mn);
      float rs = warp_sum(p0+p1);
      l[qr] = l[qr]*corr + rs;
      m[qr] = mn;
      Oa[qr][0]*=corr; Oa[qr][1]*=corr;
      Ps[row*68+c0]=p0; Ps[row*68+c1]=p1;
    }
    __syncwarp();
#pragma unroll
    for (int k4=0;k4<16;k4++){
      float vv0[4], vv1[4];
#pragma unroll
      for (int kk=0;kk<4;kk++){
        vv0[kk]=Vs[(k4*4+kk)*68+c0];
        vv1[kk]=Vs[(k4*4+kk)*68+c1];
      }
#pragma unroll
      for (int qr=0;qr<8;qr++){
        float4 pv = *(const float4*)(Ps + (warp*8+qr)*68 + k4*4);
        Oa[qr][0] += pv.x*vv0[0] + pv.y*vv0[1] + pv.z*vv0[2] + pv.w*vv0[3];
        Oa[qr][1] += pv.x*vv1[0] + pv.y*vv1[1] + pv.z*vv1[2] + pv.w*vv1[3];
      }
    }
  }
  __syncthreads();
#pragma unroll
  for (int qr=0;qr<8;qr++){
    int row = warp*8+qr;
    float invl = 1.f/l[qr];
    Ps[row*68+c0]=Oa[qr][0]*invl;
    Ps[row*68+c1]=Oa[qr][1]*invl;
  }
  __syncthreads();
  for (int e=tid;e<64*64;e+=256){
    int r=e>>6, d=e&63;
    O[(tok0 + qbase + r)*DM + h*DHEAD + d] = Ps[r*68+d];
  }
}

__global__ __launch_bounds__(256) void dawn_aux(float* __restrict__ out, int out_size){
  if (out_size <= TOK*DM) return;
  int tid = threadIdx.x;
  __shared__ float sred[32];
  float a = 0.f;
  const float invT = 1.f/(float)TOK;
  for (int i=tid;i<4*NC;i+=256){
    float d = g_cfreq[i]*invT - 1.f/(float)NC;
    a += d*d*(float)NC;
  }
  for (int i=tid;i<NQK;i+=256){
    float d;
    d = g_nfreqQ[i]*invT - 1.f/(float)NQK; a += d*d*(float)NQK;
    d = g_nfreqK[i]*invT - 1.f/(float)NQK; a += d*d*(float)NQK;
    d = g_nfreqV[i]*invT - 1.f/(float)NV;  a += d*d*(float)NV;
  }
  for (int i=tid;i<NKNOW;i+=256){
    float d = g_nfreqKn[i]*invT - 1.f/(float)NKNOW;
    a += d*d*(float)NKNOW;
  }
  float tot = block_sum(a, sred);
  if (tid==0) out[TOK*DM] = tot;
}

#define GATEB_SMEM (2*128*68*4)

extern "C" void kernel_launch(void* const* d_in, const int* in_sizes, int n_in,
                              void* d_out, int out_size){
  const float* x           = (const float*)d_in[0];
  const float* neuron_emb  = (const float*)d_in[1];
  const float* proj_attn_k = (const float*)d_in[2];
  const float* proj_attn_b = (const float*)d_in[3];
  const float* tau_attn_k  = (const float*)d_in[4];
  const float* tau_attn_b  = (const float*)d_in[5];
  const float* proj_know_k = (const float*)d_in[6];
  const float* proj_know_b = (const float*)d_in[7];
  const float* tau_know_k  = (const float*)d_in[8];
  const float* tau_know_b  = (const float*)d_in[9];
  const float* ce_qk       = (const float*)d_in[10];
  const float* ce_v        = (const float*)d_in[11];
  const float* ce_know     = (const float*)d_in[12];
  const float* qk_neurons  = (const float*)d_in[13];
  const float* v_neurons   = (const float*)d_in[14];
  const float* know_neurons= (const float*)d_in[15];
  const float* expand_O    = (const float*)d_in[16];
  const float* ln1s = (const float*)d_in[17];
  const float* ln1b = (const float*)d_in[18];
  const float* ln2s = (const float*)d_in[19];
  const float* ln2b = (const float*)d_in[20];
  float* out = (float*)d_out;

  static bool attr_done = false;
  if (!attr_done){
    cudaFuncSetAttribute(dawn_attn, cudaFuncAttributeMaxDynamicSharedMemorySize, ATTN_SMEM);
    cudaFuncSetAttribute(dawn_gateB<64>,  cudaFuncAttributeMaxDynamicSharedMemorySize, GATEB_SMEM);
    cudaFuncSetAttribute(dawn_gateB<128>, cudaFuncAttributeMaxDynamicSharedMemorySize, GATEB_SMEM);
    attr_done = true;
  }

  float *p_embn,*p_ceqk,*p_cev,*p_ceknow,*p_h1,*p_hall,*p_tau,*p_tauknow;
  float *p_Q,*p_K,*p_V,*p_attnpre,*p_x2,*p_h2,*p_hknow,*p_seg;
  int *p_idsQ,*p_idsK,*p_idsV,*p_idsKn,*p_cntQ,*p_cntK,*p_cntV,*p_cntKn;
  int *p_ccount,*p_clist,*p_top8;
  float *p_valsQ,*p_valsK,*p_valsV,*p_valsKn,*p_cfreq,*p_nfreqQ,*p_nfreqK,*p_nfreqV,*p_nfreqKn;
  cudaGetSymbolAddress((void**)&p_embn, g_embn);
  cudaGetSymbolAddress((void**)&p_ceqk, g_ceqk);
  cudaGetSymbolAddress((void**)&p_cev, g_cev);
  cudaGetSymbolAddress((void**)&p_ceknow, g_ceknow);
  cudaGetSymbolAddress((void**)&p_h1, g_h1);
  cudaGetSymbolAddress((void**)&p_hall, g_hall);
  cudaGetSymbolAddress((void**)&p_tau, g_tau);
  cudaGetSymbolAddress((void**)&p_tauknow, g_tauknow);
  cudaGetSymbolAddress((void**)&p_Q, g_Q);
  cudaGetSymbolAddress((void**)&p_K, g_K);
  cudaGetSymbolAddress((void**)&p_V, g_V);
  cudaGetSymbolAddress((void**)&p_attnpre, g_attnpre);
  cudaGetSymbolAddress((void**)&p_x2, g_x2);
  cudaGetSymbolAddress((void**)&p_h2, g_h2);
  cudaGetSymbolAddress((void**)&p_hknow, g_hknow);
  cudaGetSymbolAddress((void**)&p_seg, g_seg);
  cudaGetSymbolAddress((void**)&p_idsQ, g_idsQ);
  cudaGetSymbolAddress((void**)&p_idsK, g_idsK);
  cudaGetSymbolAddress((void**)&p_idsV, g_idsV);
  cudaGetSymbolAddress((void**)&p_idsKn, g_idsKn);
  cudaGetSymbolAddress((void**)&p_valsQ, g_valsQ);
  cudaGetSymbolAddress((void**)&p_valsK, g_valsK);
  cudaGetSymbolAddress((void**)&p_valsV, g_valsV);
  cudaGetSymbolAddress((void**)&p_valsKn, g_valsKn);
  cudaGetSymbolAddress((void**)&p_cntQ, g_cntQ);
  cudaGetSymbolAddress((void**)&p_cntK, g_cntK);
  cudaGetSymbolAddress((void**)&p_cntV, g_cntV);
  cudaGetSymbolAddress((void**)&p_cntKn, g_cntKn);
  cudaGetSymbolAddress((void**)&p_cfreq, g_cfreq);
  cudaGetSymbolAddress((void**)&p_nfreqQ, g_nfreqQ);
  cudaGetSymbolAddress((void**)&p_nfreqK, g_nfreqK);
  cudaGetSymbolAddress((void**)&p_nfreqV, g_nfreqV);
  cudaGetSymbolAddress((void**)&p_nfreqKn, g_nfreqKn);
  cudaGetSymbolAddress((void**)&p_ccount, g_ccount);
  cudaGetSymbolAddress((void**)&p_clist, g_clist);
  cudaGetSymbolAddress((void**)&p_top8, g_top8);

  // 1: LN1 (+ zero scratch)   2: tau   3: row-normalize   4: proj GEMM (profiled slot)
  dawn_ln<<<TOK,256>>>(x, ln1s, ln1b, p_h1, 1);
  dawn_tau<<<TOK,256>>>(p_h1, tau_attn_k, tau_attn_b, p_tau, 3);
  dawn_normall<<<(NQK+NV+NKNOW+3*NC)/8,256>>>(neuron_emb, ce_qk, ce_v, ce_know);
  dawn_bgemm<true,false><<<dim3(6,32),256>>>(p_h1, proj_attn_k, proj_attn_b, nullptr, p_hall, TOK, 3*DS, DM);

  // Q gate
  dawn_gateA<<<TOK,256>>>(p_hall, 3*DS, 0, p_ceqk, p_cfreq+0, p_top8+0*TOK*KC, p_ccount+0*NC, p_clist+0*NC*TOK);
  dawn_gateB<64><<<dim3(64,NC,1),256,GATEB_SMEM>>>(p_hall, 3*DS, 0, p_tau, 3, 0, p_embn, p_clist+0*NC*TOK, p_ccount+0*NC, p_seg);
  dawn_gateC<64><<<TOK,256>>>(p_seg, p_top8+0*TOK*KC, p_idsQ, p_valsQ, p_cntQ, p_nfreqQ);
  dawn_emit<<<TOK,256>>>(p_h1, qk_neurons, p_idsQ, p_valsQ, p_cntQ, NA_QKV, p_Q, nullptr);

  // K gate
  dawn_gateA<<<TOK,256>>>(p_hall, 3*DS, 128, p_ceqk, p_cfreq+64, p_top8+1*TOK*KC, p_ccount+1*NC, p_clist+1*NC*TOK);
  dawn_gateB<64><<<dim3(64,NC,1),256,GATEB_SMEM>>>(p_hall, 3*DS, 128, p_tau, 3, 1, p_embn, p_clist+1*NC*TOK, p_ccount+1*NC, p_seg);
  dawn_gateC<64><<<TOK,256>>>(p_seg, p_top8+1*TOK*KC, p_idsK, p_valsK, p_cntK, p_nfreqK);
  dawn_emit<<<TOK,256>>>(p_h1, qk_neurons, p_idsK, p_valsK, p_cntK, NA_QKV, p_K, nullptr);

  // V gate
  dawn_gateA<<<TOK,256>>>(p_hall, 3*DS, 256, p_cev, p_cfreq+128, p_top8+2*TOK*KC, p_ccount+2*NC, p_clist+2*NC*TOK);
  dawn_gateB<64><<<dim3(64,NC,1),256,GATEB_SMEM>>>(p_hall, 3*DS, 256, p_tau, 3, 2, p_embn+(size_t)NQK*DS, p_clist+2*NC*TOK, p_ccount+2*NC, p_seg);
  dawn_gateC<64><<<TOK,256>>>(p_seg, p_top8+2*TOK*KC, p_idsV, p_valsV, p_cntV, p_nfreqV);
  dawn_emit<<<TOK,256>>>(p_h1, v_neurons, p_idsV, p_valsV, p_cntV, NA_QKV, p_V, nullptr);

  // attention + output projection + residual
  dawn_attn<<<dim3(16,64),256,ATTN_SMEM>>>(p_Q, p_K, p_V, p_attnpre);
  dawn_bgemm<false,true><<<dim3(16,32),256>>>(p_attnpre, expand_O, nullptr, x, p_x2, TOK, DM, DM);

  // knowledge path
  dawn_ln<<<TOK,256>>>(p_x2, ln2s, ln2b, p_h2, 0);
  dawn_bgemm<true,false><<<dim3(2,32),256>>>(p_h2, proj_know_k, proj_know_b, nullptr, p_hknow, TOK, DS, DM);
  dawn_tau<<<TOK,256>>>(p_h2, tau_know_k, tau_know_b, p_tauknow, 1);

  dawn_gateA<<<TOK,256>>>(p_hknow, DS, 0, p_ceknow, p_cfreq+192, p_top8+3*TOK*KC, p_ccount+3*NC, p_clist+3*NC*TOK);
  dawn_gateB<128><<<dim3(64,NC,2),256,GATEB_SMEM>>>(p_hknow, DS, 0, p_tauknow, 1, 0, p_embn+(size_t)(NQK+NV)*DS, p_clist+3*NC*TOK, p_ccount+3*NC, p_seg);
  dawn_gateC<128><<<TOK,256>>>(p_seg, p_top8+3*TOK*KC, p_idsKn, p_valsKn, p_cntKn, p_nfreqKn);
  dawn_emit<<<TOK,256>>>(p_h2, know_neurons, p_idsKn, p_valsKn, p_cntKn, NA_KNOW, out, p_x2);

  dawn_aux<<<1,256>>>(out, out_size);
}